// round 5
// baseline (speedup 1.0000x reference)
#include <cuda_runtime.h>
#include <cuda_fp16.h>
#include <cstdint>

#define B_ 16
#define C_ 256
#define N_ 4096
#define M_ 1024
#define EPS_ 1e-5f
typedef long long ll;

// ---------------- scratch ----------------
__device__ float g_xT[(ll)B_ * N_ * C_];
__device__ float g_xm[B_ * C_];
__device__ float g_score[B_ * N_];
__device__ int   g_idx[2 * B_ * M_];
__device__ double g_sum[C_];
__device__ double g_sumsq[C_];
__device__ float g_bnw[C_];
__device__ float g_bnb[C_];

__device__ __half g_xTh[(ll)B_ * N_ * C_];
__device__ __half g_ctxh[2LL * B_ * M_ * C_];
__device__ __half g_Qh[(ll)B_ * N_ * C_];
__device__ __half g_Kh[(ll)B_ * M_ * C_];
__device__ __half g_Vth[(ll)B_ * C_ * M_];
__device__ __half g_Sh[(ll)B_ * N_ * M_];
__device__ __half g_Yh[(ll)B_ * N_ * C_];
__device__ __half g_Zh[(ll)B_ * N_ * 2 * C_];
__device__ __half g_Wh[10 * C_ * C_];

// ---------------- PTX ----------------
__device__ __forceinline__ void cp16(uint32_t dst, const void* src) {
    asm volatile("cp.async.cg.shared.global [%0], [%1], 16;" :: "r"(dst), "l"(src));
}
__device__ __forceinline__ void cp_commit() { asm volatile("cp.async.commit_group;"); }
template <int Nw> __device__ __forceinline__ void cp_wait() {
    asm volatile("cp.async.wait_group %0;" :: "n"(Nw));
}
__device__ __forceinline__ void ldsm_x4(uint32_t* r, uint32_t a) {
    asm volatile("ldmatrix.sync.aligned.m8n8.x4.shared.b16 {%0,%1,%2,%3}, [%4];"
        : "=r"(r[0]), "=r"(r[1]), "=r"(r[2]), "=r"(r[3]) : "r"(a));
}
__device__ __forceinline__ void ldsm_x2(uint32_t* r, uint32_t a) {
    asm volatile("ldmatrix.sync.aligned.m8n8.x2.shared.b16 {%0,%1}, [%2];"
        : "=r"(r[0]), "=r"(r[1]) : "r"(a));
}
__device__ __forceinline__ void mma_f16(float* c, const uint32_t* a, const uint32_t* b) {
    asm volatile("mma.sync.aligned.m16n8k16.row.col.f32.f16.f16.f32 "
        "{%0,%1,%2,%3}, {%4,%5,%6,%7}, {%8,%9}, {%0,%1,%2,%3};"
        : "+f"(c[0]), "+f"(c[1]), "+f"(c[2]), "+f"(c[3])
        : "r"(a[0]), "r"(a[1]), "r"(a[2]), "r"(a[3]), "r"(b[0]), "r"(b[1]));
}

// ---------------- small kernels (unchanged, proven) ----------------
__global__ void transpose_kernel(const float* __restrict__ x) {
    __shared__ float t[32][33];
    int b = blockIdx.z, n0 = blockIdx.x * 32, c0 = blockIdx.y * 32;
    int tx = threadIdx.x, ty = threadIdx.y;
    const float* xp = x + (ll)b * C_ * N_;
    float* xtp = g_xT + (ll)b * N_ * C_;
    __half* xhp = g_xTh + (ll)b * N_ * C_;
#pragma unroll
    for (int i = 0; i < 32; i += 8)
        t[ty + i][tx] = xp[(ll)(c0 + ty + i) * N_ + n0 + tx];
    __syncthreads();
#pragma unroll
    for (int i = 0; i < 32; i += 8) {
        float v = t[tx][ty + i];
        xtp[(ll)(n0 + ty + i) * C_ + c0 + tx] = v;
        xhp[(ll)(n0 + ty + i) * C_ + c0 + tx] = __float2half_rn(v);
    }
}

__global__ void mean_kernel(const float* __restrict__ x) {
    int c = blockIdx.x, b = blockIdx.y, t = threadIdx.x;
    const float* p = x + ((ll)b * C_ + c) * N_;
    float s = 0.f;
    for (int i = t; i < N_; i += 256) s += p[i];
    __shared__ float sh[256];
    sh[t] = s; __syncthreads();
    for (int w = 128; w > 0; w >>= 1) { if (t < w) sh[t] += sh[t + w]; __syncthreads(); }
    if (t == 0) g_xm[b * C_ + c] = sh[0] * (1.0f / N_);
}

__global__ void score_kernel2() {
    int b = blockIdx.y;
    int w = threadIdx.x >> 5, lane = threadIdx.x & 31;
    int n = blockIdx.x * 8 + w;
    const float4* row = (const float4*)(g_xT + ((ll)b * N_ + n) * C_);
    const float4* mrow = (const float4*)(g_xm + b * C_);
    float s = 0.f;
#pragma unroll
    for (int j = lane; j < 64; j += 32) {
        float4 v = row[j], m = mrow[j];
        float dx = v.x - m.x, dy = v.y - m.y, dz = v.z - m.z, dw = v.w - m.w;
        s += dx * dx + dy * dy + dz * dz + dw * dw;
    }
#pragma unroll
    for (int o = 16; o; o >>= 1) s += __shfl_xor_sync(0xffffffffu, s, o);
    if (lane == 0) g_score[b * N_ + n] = s;
}

__global__ void sort_kernel() {
    __shared__ float sv[N_];
    __shared__ int   si[N_];
    int b = blockIdx.x, t = threadIdx.x;
    for (int i = t; i < N_; i += 1024) { sv[i] = g_score[b * N_ + i]; si[i] = i; }
    __syncthreads();
    for (int k = 2; k <= N_; k <<= 1)
        for (int j = k >> 1; j > 0; j >>= 1) {
            for (int i = t; i < N_; i += 1024) {
                int ixj = i ^ j;
                if (ixj > i) {
                    bool desc = ((i & k) == 0);
                    float a = sv[i], c = sv[ixj];
                    if (desc ? (a < c) : (a > c)) {
                        sv[i] = c; sv[ixj] = a;
                        int ta = si[i]; si[i] = si[ixj]; si[ixj] = ta;
                    }
                }
            }
            __syncthreads();
        }
    for (int m = t; m < M_; m += 1024) {
        g_idx[0 * B_ * M_ + b * M_ + m] = si[m];
        g_idx[1 * B_ * M_ + b * M_ + m] = si[N_ - M_ + m];
    }
}

__global__ void gather_kernel2() {
    int side = blockIdx.z, b = blockIdx.y;
    int m = blockIdx.x * 4 + (threadIdx.x >> 6);
    int c4 = threadIdx.x & 63;
    int j = g_idx[side * B_ * M_ + b * M_ + m];
    float4 v = ((const float4*)(g_xT + ((ll)b * N_ + j) * C_))[c4];
    __half2* dst = (__half2*)(g_ctxh + (((ll)side * B_ + b) * M_ + m) * C_);
    dst[c4 * 2] = __floats2half2_rn(v.x, v.y);
    dst[c4 * 2 + 1] = __floats2half2_rn(v.z, v.w);
}

__global__ void f2h_kernel(const float* __restrict__ s, __half* __restrict__ d, int n) {
    int i = blockIdx.x * 256 + threadIdx.x;
    if (i < n) d[i] = __float2half_rn(s[i]);
}

__global__ void softmax_kernel() {
    int t = threadIdx.x;
    ll row = ((ll)blockIdx.y * N_ + blockIdx.x) * M_;
    uint2* p = (uint2*)(g_Sh + row);
    uint2 raw = p[t];
    __half2 h0 = *(__half2*)&raw.x, h1 = *(__half2*)&raw.y;
    float2 a = __half22float2(h0), bb = __half22float2(h1);
    __shared__ float sh[256];
    float mx = fmaxf(fmaxf(a.x, a.y), fmaxf(bb.x, bb.y));
    sh[t] = mx; __syncthreads();
    for (int w = 128; w > 0; w >>= 1) { if (t < w) sh[t] = fmaxf(sh[t], sh[t + w]); __syncthreads(); }
    float m = sh[0]; __syncthreads();
    a.x = expf(a.x - m); a.y = expf(a.y - m);
    bb.x = expf(bb.x - m); bb.y = expf(bb.y - m);
    sh[t] = a.x + a.y + bb.x + bb.y; __syncthreads();
    for (int w = 128; w > 0; w >>= 1) { if (t < w) sh[t] += sh[t + w]; __syncthreads(); }
    float inv = 1.0f / sh[0];
    h0 = __floats2half2_rn(a.x * inv, a.y * inv);
    h1 = __floats2half2_rn(bb.x * inv, bb.y * inv);
    raw.x = *(uint32_t*)&h0; raw.y = *(uint32_t*)&h1;
    p[t] = raw;
}

__global__ void bn_zero() {
    int t = threadIdx.x;
    if (t < C_) { g_sum[t] = 0.0; g_sumsq[t] = 0.0; }
}

__global__ void bn_stats(const float* __restrict__ pre) {
    int d = blockIdx.x, b = blockIdx.y, t = threadIdx.x;
    const float* p = pre + ((ll)b * C_ + d) * N_;
    float s = 0.f, s2 = 0.f;
    for (int i = t; i < N_; i += 256) { float v = p[i]; s += v; s2 += v * v; }
    __shared__ float sh[256];
    sh[t] = s; __syncthreads();
    for (int w = 128; w > 0; w >>= 1) { if (t < w) sh[t] += sh[t + w]; __syncthreads(); }
    float ts = sh[0]; __syncthreads();
    sh[t] = s2; __syncthreads();
    for (int w = 128; w > 0; w >>= 1) { if (t < w) sh[t] += sh[t + w]; __syncthreads(); }
    float ts2 = sh[0];
    if (t == 0) { atomicAdd(&g_sum[d], (double)ts); atomicAdd(&g_sumsq[d], (double)ts2); }
}

__global__ void bn_finalize(const float* __restrict__ gamma, const float* __restrict__ beta) {
    int d = threadIdx.x;
    double cnt = (double)B_ * N_;
    double mu = g_sum[d] / cnt;
    double var = g_sumsq[d] / cnt - mu * mu;
    float w = gamma[d] * rsqrtf((float)var + EPS_);
    g_bnw[d] = w;
    g_bnb[d] = beta[d] - (float)mu * w;
}

__global__ void bn_final(float* __restrict__ out) {
    int n = blockIdx.x * 256 + threadIdx.x;
    int d = blockIdx.y, b = blockIdx.z;
    ll o = ((ll)b * C_ + d) * N_ + n;
    float v = out[o] * g_bnw[d] + g_bnb[d];
    out[o] = v > 0.f ? v : 0.f;
}

// ---------------- fp16 TN GEMM: 256x128 tiles, k-chunk 64 halves ----------------
// C[i,j] = scale*sum_k A[i*lda+k]*B[j*ldb+k] (+bias)(+R[i*ldr+j])
// 8 warps in 4x2; warp tile 64x64. smem: per stage A 32KB + B 16KB, 2 stages = 96KB.
#define STG_BYTES 49152
#define B_OFF 32768

template <int BIAS, bool RES, typename OutT>
__global__ __launch_bounds__(256, 1)
void gemm_tn(const __half* __restrict__ A, ll sA, int lda,
             const __half* __restrict__ Bg, ll sB, int ldb,
             OutT* __restrict__ Cm, ll sC, int ldc, int Kd,
             const float* __restrict__ bias,
             const float* __restrict__ R, ll sR, int ldr, float scale) {
    extern __shared__ char smc[];
    const uint32_t smu = (uint32_t)__cvta_generic_to_shared(smc);
    const int bz = blockIdx.z;
    A += (ll)bz * sA; Bg += (ll)bz * sB; Cm += (ll)bz * sC;
    if (RES) R += (ll)bz * sR;
    const int row0 = blockIdx.y * 256, col0 = blockIdx.x * 128;
    const int tid = threadIdx.x, lane = tid & 31, warp = tid >> 5;
    const int wm = warp >> 1, wn = warp & 1;
    const int rA = lane & 15, selA = lane >> 4;
    const int tb = lane & 15, rB = tb & 7, midB = tb >> 3;

    float acc[4][8][4];
#pragma unroll
    for (int i = 0; i < 4; i++)
#pragma unroll
        for (int j = 0; j < 8; j++)
#pragma unroll
            for (int q = 0; q < 4; q++) acc[i][j][q] = 0.f;

    const int nT = Kd / 64;
    // stage 0: A 256 rows (2048 f4), B 128 rows (1024 f4)
#pragma unroll
    for (int r = 0; r < 8; r++) {
        int lin = tid + r * 256;
        int row = lin >> 3, f4 = lin & 7;
        uint32_t so = (uint32_t)((row * 8 + (f4 ^ (row & 7))) * 16);
        cp16(smu + so, A + (ll)(row0 + row) * lda + f4 * 8);
    }
#pragma unroll
    for (int r = 0; r < 4; r++) {
        int lin = tid + r * 256;
        int row = lin >> 3, f4 = lin & 7;
        uint32_t so = (uint32_t)((row * 8 + (f4 ^ (row & 7))) * 16);
        cp16(smu + B_OFF + so, Bg + (ll)(col0 + row) * ldb + f4 * 8);
    }
    cp_commit();

    for (int t = 0; t < nT; t++) {
        if (t + 1 < nT) {
            int st = (t + 1) & 1, k0 = (t + 1) * 64;
            uint32_t sb = (uint32_t)(st * STG_BYTES);
#pragma unroll
            for (int r = 0; r < 8; r++) {
                int lin = tid + r * 256;
                int row = lin >> 3, f4 = lin & 7;
                uint32_t so = (uint32_t)((row * 8 + (f4 ^ (row & 7))) * 16);
                cp16(smu + sb + so, A + (ll)(row0 + row) * lda + k0 + f4 * 8);
            }
#pragma unroll
            for (int r = 0; r < 4; r++) {
                int lin = tid + r * 256;
                int row = lin >> 3, f4 = lin & 7;
                uint32_t so = (uint32_t)((row * 8 + (f4 ^ (row & 7))) * 16);
                cp16(smu + sb + B_OFF + so, Bg + (ll)(col0 + row) * ldb + k0 + f4 * 8);
            }
            cp_commit(); cp_wait<1>();
        } else cp_wait<0>();
        __syncthreads();

        uint32_t Au = smu + (uint32_t)((t & 1) * STG_BYTES);
        uint32_t Bu = Au + B_OFF;
#pragma unroll
        for (int kt = 0; kt < 4; kt++) {
            uint32_t af[4][4], bf[8][2];
#pragma unroll
            for (int mt = 0; mt < 4; mt++) {
                int row = wm * 64 + mt * 16 + rA;
                int u = kt * 2 + selA;
                ldsm_x4(af[mt], Au + (uint32_t)((row * 8 + (u ^ (row & 7))) * 16));
            }
#pragma unroll
            for (int nt = 0; nt < 8; nt++) {
                int row = wn * 64 + nt * 8 + rB;
                int u = kt * 2 + midB;
                ldsm_x2(bf[nt], Bu + (uint32_t)((row * 8 + (u ^ (row & 7))) * 16));
            }
#pragma unroll
            for (int mt = 0; mt < 4; mt++)
#pragma unroll
                for (int nt = 0; nt < 8; nt++)
                    mma_f16(acc[mt][nt], af[mt], bf[nt]);
        }
        __syncthreads();
    }

    const int gr = lane >> 2, gc = (lane & 3) * 2;
#pragma unroll
    for (int mt = 0; mt < 4; mt++) {
        int r0 = row0 + wm * 64 + mt * 16 + gr;
#pragma unroll
        for (int nt = 0; nt < 8; nt++) {
            int col = col0 + wn * 64 + nt * 8 + gc;
            float v0x = acc[mt][nt][0] * scale, v0y = acc[mt][nt][1] * scale;
            float v1x = acc[mt][nt][2] * scale, v1y = acc[mt][nt][3] * scale;
            if (BIAS == 1) {
                float bx = bias[col], by = bias[col + 1];
                v0x += bx; v0y += by; v1x += bx; v1y += by;
            } else if (BIAS == 2) {
                float b0v = bias[r0], b1v = bias[r0 + 8];
                v0x += b0v; v0y += b0v; v1x += b1v; v1y += b1v;
            }
            if (RES) {
                float2 ra = *(const float2*)&R[(ll)r0 * ldr + col];
                float2 rb = *(const float2*)&R[(ll)(r0 + 8) * ldr + col];
                v0x += ra.x; v0y += ra.y; v1x += rb.x; v1y += rb.y;
            }
            if constexpr (sizeof(OutT) == 2) {
                *(__half2*)((__half*)Cm + (ll)r0 * ldc + col) = __floats2half2_rn(v0x, v0y);
                *(__half2*)((__half*)Cm + (ll)(r0 + 8) * ldc + col) = __floats2half2_rn(v1x, v1y);
            } else {
                *(float2*)((float*)Cm + (ll)r0 * ldc + col) = make_float2(v0x, v0y);
                *(float2*)((float*)Cm + (ll)(r0 + 8) * ldc + col) = make_float2(v1x, v1y);
            }
        }
    }
}

template <int BIAS, bool RES, typename OutT>
static void launch_tn(const __half* A, ll sA, int lda,
                      const __half* Bg, ll sB, int ldb,
                      OutT* Cm, ll sC, int ldc,
                      int Md, int Nd, int Kd,
                      const float* bias,
                      const float* R, ll sR, int ldr,
                      float scale, int batch) {
    cudaFuncSetAttribute(gemm_tn<BIAS, RES, OutT>,
                         cudaFuncAttributeMaxDynamicSharedMemorySize, 2 * STG_BYTES);
    dim3 grid(Nd / 128, Md / 256, batch);
    gemm_tn<BIAS, RES, OutT><<<grid, 256, 2 * STG_BYTES>>>(
        A, sA, lda, Bg, sB, ldb, Cm, sC, ldc, Kd, bias, R, sR, ldr, scale);
}

// ---------------- driver ----------------
extern "C" void kernel_launch(void* const* d_in, const int* in_sizes, int n_in,
                              void* d_out, int out_size) {
    const float* x = (const float*)d_in[0];
    int pb = (n_in > 1 && in_sizes[1] == 1) ? 2 : 1;
    const float* P[20];
    for (int i = 0; i < 20; i++) P[i] = (const float*)d_in[pb + i];
    float* out = (float*)d_out;

    float *xT;
    __half *xTh, *ctxh, *Qh, *Kh, *Vth, *Sh, *Yh, *Zh, *Wh;
    cudaGetSymbolAddress((void**)&xT, g_xT);
    cudaGetSymbolAddress((void**)&xTh, g_xTh);
    cudaGetSymbolAddress((void**)&ctxh, g_ctxh);
    cudaGetSymbolAddress((void**)&Qh, g_Qh);
    cudaGetSymbolAddress((void**)&Kh, g_Kh);
    cudaGetSymbolAddress((void**)&Vth, g_Vth);
    cudaGetSymbolAddress((void**)&Sh, g_Sh);
    cudaGetSymbolAddress((void**)&Yh, g_Yh);
    cudaGetSymbolAddress((void**)&Zh, g_Zh);
    cudaGetSymbolAddress((void**)&Wh, g_Wh);

    const int CC = C_ * C_;

    transpose_kernel<<<dim3(N_ / 32, C_ / 32, B_), dim3(32, 8)>>>(x);
    mean_kernel<<<dim3(C_, B_), 256>>>(x);
    score_kernel2<<<dim3(N_ / 8, B_), 256>>>();
    sort_kernel<<<B_, 1024>>>();
    gather_kernel2<<<dim3(M_ / 4, B_, 2), 256>>>();

    for (int s = 0; s < 2; s++)
        for (int w = 0; w < 4; w++)
            f2h_kernel<<<CC / 256, 256>>>(P[8 * s + 2 * w], Wh + (s * 4 + w) * CC, CC);
    f2h_kernel<<<(2 * CC) / 256, 256>>>(P[16], Wh + 8 * CC, 2 * CC);

    for (int s = 0; s < 2; s++) {
        const __half* Wq = Wh + (s * 4 + 0) * CC; const float* bq = P[8 * s + 1];
        const __half* Wk = Wh + (s * 4 + 1) * CC; const float* bk = P[8 * s + 3];
        const __half* Wv = Wh + (s * 4 + 2) * CC; const float* bv = P[8 * s + 5];
        const __half* Wo = Wh + (s * 4 + 3) * CC; const float* bo = P[8 * s + 7];
        const __half* ctxp = ctxh + (ll)s * B_ * M_ * C_;

        launch_tn<1, false>(xTh, (ll)N_ * C_, C_, Wq, 0, C_,
                            Qh, (ll)N_ * C_, C_, N_, C_, C_, bq, nullptr, 0, 0, 1.f, B_);
        launch_tn<1, false>(ctxp, (ll)M_ * C_, C_, Wk, 0, C_,
                            Kh, (ll)M_ * C_, C_, M_, C_, C_, bk, nullptr, 0, 0, 1.f, B_);
        launch_tn<2, false>(Wv, 0, C_, ctxp, (ll)M_ * C_, C_,
                            Vth, (ll)C_ * M_, M_, C_, M_, C_, bv, nullptr, 0, 0, 1.f, B_);
        launch_tn<0, false>(Qh, (ll)N_ * C_, C_, Kh, (ll)M_ * C_, C_,
                            Sh, (ll)N_ * M_, M_, N_, M_, C_, nullptr, nullptr, 0, 0, 1.f / 16.f, B_);
        softmax_kernel<<<dim3(N_, B_), 256>>>();
        launch_tn<0, false>(Sh, (ll)N_ * M_, M_, Vth, (ll)C_ * M_, M_,
                            Yh, (ll)N_ * C_, C_, N_, C_, M_, nullptr, nullptr, 0, 0, 1.f, B_);
        launch_tn<1, true>(Yh, (ll)N_ * C_, C_, Wo, 0, C_,
                           Zh + s * C_, (ll)N_ * 2 * C_, 2 * C_,
                           N_, C_, C_, bo, xT, (ll)N_ * C_, C_, 1.f, B_);
    }

    launch_tn<2, false>(Wh + 8 * CC, 0, 2 * C_, Zh, (ll)N_ * 2 * C_, 2 * C_,
                        out, (ll)C_ * N_, N_, C_, N_, 2 * C_,
                        P[17], nullptr, 0, 0, 1.f, B_);

    bn_zero<<<1, 256>>>();
    bn_stats<<<dim3(C_, B_), 256>>>(out);
    bn_finalize<<<1, 256>>>(P[18], P[19]);
    bn_final<<<dim3(N_ / 256, C_, B_), 256>>>(out);
}

// round 7
// speedup vs baseline: 1.1995x; 1.1995x over previous
#include <cuda_runtime.h>
#include <cuda_fp16.h>
#include <cstdint>

#define B_ 16
#define C_ 256
#define N_ 4096
#define M_ 1024
#define EPS_ 1e-5f
typedef long long ll;

// ---------------- scratch ----------------
__device__ float g_xm[B_ * C_];
__device__ float g_score[B_ * N_];
__device__ int   g_idx[2 * B_ * M_];
__device__ double g_sum[C_];
__device__ double g_sumsq[C_];
__device__ float g_bnw[C_];
__device__ float g_bnb[C_];
__device__ float g_bp[4 * 512];                    // packed biases: bq2|bk2|bv2|bo2

__device__ __half g_xTh[(ll)B_ * N_ * C_];         // [b][n][c]
__device__ __half g_ctxh[2LL * B_ * M_ * C_];      // [side][b][m][c]
__device__ __half g_Qh[(ll)B_ * N_ * 2 * C_];      // [b][n][512] (sharp|gentle)
__device__ __half g_Kh[2LL * B_ * M_ * C_];        // [side][b][m][d]
__device__ __half g_Vth[2LL * B_ * C_ * M_];       // [side][b][d][m]
__device__ __half g_Sh[2LL * B_ * N_ * M_];        // [side][b][n][m]
__device__ __half g_Yh[2LL * B_ * N_ * C_];        // [side][b][n][d]
__device__ __half g_Zh[(ll)B_ * N_ * 2 * C_];      // [b][n][2C]
__device__ __half g_Ph[(ll)B_ * C_ * N_];          // pre-BN fuse output [b][d][n]
__device__ __half g_Wh[10 * C_ * C_];              // Wq_s,Wq_g,Wk_s,Wk_g,Wv_s,Wv_g,Wo_s,Wo_g,Wf

// ---------------- PTX ----------------
__device__ __forceinline__ void cp16(uint32_t dst, const void* src) {
    asm volatile("cp.async.cg.shared.global [%0], [%1], 16;" :: "r"(dst), "l"(src));
}
__device__ __forceinline__ void cp_commit() { asm volatile("cp.async.commit_group;"); }
template <int Nw> __device__ __forceinline__ void cp_wait() {
    asm volatile("cp.async.wait_group %0;" :: "n"(Nw));
}
__device__ __forceinline__ void ldsm_x4(uint32_t* r, uint32_t a) {
    asm volatile("ldmatrix.sync.aligned.m8n8.x4.shared.b16 {%0,%1,%2,%3}, [%4];"
        : "=r"(r[0]), "=r"(r[1]), "=r"(r[2]), "=r"(r[3]) : "r"(a));
}
__device__ __forceinline__ void ldsm_x2(uint32_t* r, uint32_t a) {
    asm volatile("ldmatrix.sync.aligned.m8n8.x2.shared.b16 {%0,%1}, [%2];"
        : "=r"(r[0]), "=r"(r[1]) : "r"(a));
}
__device__ __forceinline__ void mma_f16(float* c, const uint32_t* a, const uint32_t* b) {
    asm volatile("mma.sync.aligned.m16n8k16.row.col.f32.f16.f16.f32 "
        "{%0,%1,%2,%3}, {%4,%5,%6,%7}, {%8,%9}, {%0,%1,%2,%3};"
        : "+f"(c[0]), "+f"(c[1]), "+f"(c[2]), "+f"(c[3])
        : "r"(a[0]), "r"(a[1]), "r"(a[2]), "r"(a[3]), "r"(b[0]), "r"(b[1]));
}

// ---------------- small kernels ----------------
__global__ void transpose_kernel(const float* __restrict__ x) {
    __shared__ float t[32][33];
    int b = blockIdx.z, n0 = blockIdx.x * 32, c0 = blockIdx.y * 32;
    int tx = threadIdx.x, ty = threadIdx.y;
    const float* xp = x + (ll)b * C_ * N_;
    __half* xhp = g_xTh + (ll)b * N_ * C_;
#pragma unroll
    for (int i = 0; i < 32; i += 8)
        t[ty + i][tx] = xp[(ll)(c0 + ty + i) * N_ + n0 + tx];
    __syncthreads();
#pragma unroll
    for (int i = 0; i < 32; i += 8)
        xhp[(ll)(n0 + ty + i) * C_ + c0 + tx] = __float2half_rn(t[tx][ty + i]);
}

__global__ void mean_kernel(const float* __restrict__ x) {
    int c = blockIdx.x, b = blockIdx.y, t = threadIdx.x;
    const float* p = x + ((ll)b * C_ + c) * N_;
    float s = 0.f;
    for (int i = t; i < N_; i += 256) s += p[i];
    __shared__ float sh[256];
    sh[t] = s; __syncthreads();
    for (int w = 128; w > 0; w >>= 1) { if (t < w) sh[t] += sh[t + w]; __syncthreads(); }
    if (t == 0) g_xm[b * C_ + c] = sh[0] * (1.0f / N_);
}

__global__ void score_kernel(const float* __restrict__ x) {
    int n = blockIdx.x * 256 + threadIdx.x;
    int b = blockIdx.y;
    const float* px = x + (ll)b * C_ * N_;
    const float* pm = g_xm + b * C_;
    float s = 0.f;
#pragma unroll 8
    for (int c = 0; c < C_; c++) {
        float d = px[(ll)c * N_ + n] - pm[c];
        s += d * d;
    }
    g_score[b * N_ + n] = s;
}

__global__ void sort_kernel() {
    __shared__ float sv[N_];
    __shared__ int   si[N_];
    int b = blockIdx.x, t = threadIdx.x;
    for (int i = t; i < N_; i += 1024) { sv[i] = g_score[b * N_ + i]; si[i] = i; }
    __syncthreads();
    for (int k = 2; k <= N_; k <<= 1)
        for (int j = k >> 1; j > 0; j >>= 1) {
            for (int i = t; i < N_; i += 1024) {
                int ixj = i ^ j;
                if (ixj > i) {
                    bool desc = ((i & k) == 0);
                    float a = sv[i], c = sv[ixj];
                    if (desc ? (a < c) : (a > c)) {
                        sv[i] = c; sv[ixj] = a;
                        int ta = si[i]; si[i] = si[ixj]; si[ixj] = ta;
                    }
                }
            }
            __syncthreads();
        }
    for (int m = t; m < M_; m += 1024) {
        g_idx[0 * B_ * M_ + b * M_ + m] = si[m];
        g_idx[1 * B_ * M_ + b * M_ + m] = si[N_ - M_ + m];
    }
}

__global__ void gather_kernel() {
    int side = blockIdx.z, b = blockIdx.y;
    int m = blockIdx.x * 8 + (threadIdx.x >> 5);
    int c8 = threadIdx.x & 31;
    int j = g_idx[side * B_ * M_ + b * M_ + m];
    uint4 v = ((const uint4*)(g_xTh + ((ll)b * N_ + j) * C_))[c8];
    ((uint4*)(g_ctxh + (((ll)side * B_ + b) * M_ + m) * C_))[c8] = v;
}

__global__ void pack_w(const float* a0, const float* a1, const float* a2,
                       const float* a3, const float* a4, const float* a5,
                       const float* a6, const float* a7, const float* a8) {
    int i = blockIdx.x * 256 + threadIdx.x;  // 655360 total
    const float* p[9] = {a0, a1, a2, a3, a4, a5, a6, a7, a8};
    int seg = i >> 16;
    float v = (seg < 8) ? p[seg][i & 65535] : p[8][i - 524288];
    g_Wh[i] = __float2half_rn(v);
}

__global__ void pack_b(const float* b0, const float* b1, const float* b2,
                       const float* b3, const float* b4, const float* b5,
                       const float* b6, const float* b7) {
    int i = threadIdx.x + blockIdx.x * 256;  // 2048
    const float* p[8] = {b0, b1, b2, b3, b4, b5, b6, b7};
    int grp = i >> 9, k = i & 511;
    g_bp[i] = p[(grp << 1) | (k >> 8)][k & 255];
}

__global__ void softmax_kernel() {
    int t = threadIdx.x;
    ll row = ((ll)blockIdx.y * N_ + blockIdx.x) * M_;
    uint2* p = (uint2*)(g_Sh + row);
    uint2 raw = p[t];
    __half2 h0 = *(__half2*)&raw.x, h1 = *(__half2*)&raw.y;
    float2 a = __half22float2(h0), bb = __half22float2(h1);
    __shared__ float sh[256];
    float mx = fmaxf(fmaxf(a.x, a.y), fmaxf(bb.x, bb.y));
    sh[t] = mx; __syncthreads();
    for (int w = 128; w > 0; w >>= 1) { if (t < w) sh[t] = fmaxf(sh[t], sh[t + w]); __syncthreads(); }
    float m = sh[0]; __syncthreads();
    a.x = expf(a.x - m); a.y = expf(a.y - m);
    bb.x = expf(bb.x - m); bb.y = expf(bb.y - m);
    sh[t] = a.x + a.y + bb.x + bb.y; __syncthreads();
    for (int w = 128; w > 0; w >>= 1) { if (t < w) sh[t] += sh[t + w]; __syncthreads(); }
    float inv = 1.0f / sh[0];
    h0 = __floats2half2_rn(a.x * inv, a.y * inv);
    h1 = __floats2half2_rn(bb.x * inv, bb.y * inv);
    raw.x = *(uint32_t*)&h0; raw.y = *(uint32_t*)&h1;
    p[t] = raw;
}

__global__ void bn_zero() {
    int t = threadIdx.x;
    if (t < C_) { g_sum[t] = 0.0; g_sumsq[t] = 0.0; }
}

__global__ void bn_finalize(const float* __restrict__ gamma, const float* __restrict__ beta) {
    int d = threadIdx.x;
    double cnt = (double)B_ * N_;
    double mu = g_sum[d] / cnt;
    double var = g_sumsq[d] / cnt - mu * mu;
    float w = gamma[d] * rsqrtf((float)var + EPS_);
    g_bnw[d] = w;
    g_bnb[d] = beta[d] - (float)mu * w;
}

__global__ void bn_final(float* __restrict__ out) {
    int n = blockIdx.x * 256 + threadIdx.x;
    int d = blockIdx.y, b = blockIdx.z;
    ll o = ((ll)b * C_ + d) * N_ + n;
    float v = __half2float(g_Ph[o]) * g_bnw[d] + g_bnb[d];
    out[o] = v > 0.f ? v : 0.f;
}

// ---------------- fp16 TN GEMM (R4 core + batch/side strides) ----------------
// z = side*16 + b (side = z>>4). C[i,j] = scale*sum_k A[i*lda+k]*B[j*ldb+k]
// (+bias[col/row + side*biasStr]) (+R[i*ldr+j] fp16). STATS: per-row double atomics.
template <int BIAS, bool RES, bool STATS, typename OutT>
__global__ __launch_bounds__(256, 2)
void gemm_tn(const __half* __restrict__ A, ll sA, ll sA2, int lda,
             const __half* __restrict__ Bg, ll sB, ll sB2, int ldb,
             OutT* __restrict__ Cm, ll sC, ll sC2, int ldc, int Kd,
             const float* __restrict__ bias, int biasStr,
             const __half* __restrict__ R, ll sR, int ldr,
             float scale, double* stS, double* stQ) {
    extern __shared__ char smc[];
    const uint32_t smu = (uint32_t)__cvta_generic_to_shared(smc);
    const int bz = blockIdx.z, side = bz >> 4, b = bz & 15;
    A += (ll)b * sA + (ll)side * sA2;
    Bg += (ll)b * sB + (ll)side * sB2;
    Cm += (ll)b * sC + (ll)side * sC2;
    if (BIAS) bias += side * biasStr;
    if (RES) R += (ll)b * sR;
    const int row0 = blockIdx.y * 128, col0 = blockIdx.x * 128;
    const int tid = threadIdx.x, lane = tid & 31, warp = tid >> 5;
    const int wm = warp >> 2, wn = warp & 3;
    const int rA = lane & 15, selA = lane >> 4;
    const int tb = lane & 15, rB = tb & 7, midB = tb >> 3;

    float acc[4][4][4];
#pragma unroll
    for (int i = 0; i < 4; i++)
#pragma unroll
        for (int j = 0; j < 4; j++)
#pragma unroll
            for (int q = 0; q < 4; q++) acc[i][j][q] = 0.f;

    const int nT = Kd / 64;
#pragma unroll
    for (int r = 0; r < 4; r++) {
        int lin = tid + r * 256;
        int row = lin >> 3, f4 = lin & 7;
        uint32_t so = (uint32_t)((row * 8 + (f4 ^ (row & 7))) * 16);
        cp16(smu + so, A + (ll)(row0 + row) * lda + f4 * 8);
        cp16(smu + 16384 + so, Bg + (ll)(col0 + row) * ldb + f4 * 8);
    }
    cp_commit();

    for (int t = 0; t < nT; t++) {
        if (t + 1 < nT) {
            int st = (t + 1) & 1, k0 = (t + 1) * 64;
#pragma unroll
            for (int r = 0; r < 4; r++) {
                int lin = tid + r * 256;
                int row = lin >> 3, f4 = lin & 7;
                uint32_t so = (uint32_t)(st * 32768 + (row * 8 + (f4 ^ (row & 7))) * 16);
                cp16(smu + so, A + (ll)(row0 + row) * lda + k0 + f4 * 8);
                cp16(smu + 16384 + so, Bg + (ll)(col0 + row) * ldb + k0 + f4 * 8);
            }
            cp_commit(); cp_wait<1>();
        } else cp_wait<0>();
        __syncthreads();

        uint32_t Au = smu + (uint32_t)((t & 1) * 32768);
        uint32_t Bu = Au + 16384;
#pragma unroll
        for (int kt = 0; kt < 4; kt++) {
            uint32_t af[4][4], bf[4][2];
#pragma unroll
            for (int mt = 0; mt < 4; mt++) {
                int row = wm * 64 + mt * 16 + rA;
                int u = kt * 2 + selA;
                ldsm_x4(af[mt], Au + (uint32_t)((row * 8 + (u ^ (row & 7))) * 16));
            }
#pragma unroll
            for (int nt = 0; nt < 4; nt++) {
                int row = wn * 32 + nt * 8 + rB;
                int u = kt * 2 + midB;
                ldsm_x2(bf[nt], Bu + (uint32_t)((row * 8 + (u ^ (row & 7))) * 16));
            }
#pragma unroll
            for (int mt = 0; mt < 4; mt++)
#pragma unroll
                for (int nt = 0; nt < 4; nt++)
                    mma_f16(acc[mt][nt], af[mt], bf[nt]);
        }
        __syncthreads();
    }

    const int gr = lane >> 2, gc = (lane & 3) * 2;
#pragma unroll
    for (int mt = 0; mt < 4; mt++) {
        int r0 = row0 + wm * 64 + mt * 16 + gr;
        float s0 = 0.f, q0 = 0.f, s1 = 0.f, q1 = 0.f;
#pragma unroll
        for (int nt = 0; nt < 4; nt++) {
            int col = col0 + wn * 32 + nt * 8 + gc;
            float v0x = acc[mt][nt][0] * scale, v0y = acc[mt][nt][1] * scale;
            float v1x = acc[mt][nt][2] * scale, v1y = acc[mt][nt][3] * scale;
            if (BIAS == 1) {
                float bx = bias[col], by = bias[col + 1];
                v0x += bx; v0y += by; v1x += bx; v1y += by;
            } else if (BIAS == 2) {
                float b0v = bias[r0], b1v = bias[r0 + 8];
                v0x += b0v; v0y += b0v; v1x += b1v; v1y += b1v;
            }
            if (RES) {
                float2 ra = __half22float2(*(const __half2*)&R[(ll)r0 * ldr + col]);
                float2 rb = __half22float2(*(const __half2*)&R[(ll)(r0 + 8) * ldr + col]);
                v0x += ra.x; v0y += ra.y; v1x += rb.x; v1y += rb.y;
            }
            if (STATS) {
                s0 += v0x + v0y; q0 += v0x * v0x + v0y * v0y;
                s1 += v1x + v1y; q1 += v1x * v1x + v1y * v1y;
            }
            if constexpr (sizeof(OutT) == 2) {
                *(__half2*)((__half*)Cm + (ll)r0 * ldc + col) = __floats2half2_rn(v0x, v0y);
                *(__half2*)((__half*)Cm + (ll)(r0 + 8) * ldc + col) = __floats2half2_rn(v1x, v1y);
            } else {
                *(float2*)((float*)Cm + (ll)r0 * ldc + col) = make_float2(v0x, v0y);
                *(float2*)((float*)Cm + (ll)(r0 + 8) * ldc + col) = make_float2(v1x, v1y);
            }
        }
        if (STATS) {
            s0 += __shfl_xor_sync(0xffffffffu, s0, 1); s0 += __shfl_xor_sync(0xffffffffu, s0, 2);
            q0 += __shfl_xor_sync(0xffffffffu, q0, 1); q0 += __shfl_xor_sync(0xffffffffu, q0, 2);
            s1 += __shfl_xor_sync(0xffffffffu, s1, 1); s1 += __shfl_xor_sync(0xffffffffu, s1, 2);
            q1 += __shfl_xor_sync(0xffffffffu, q1, 1); q1 += __shfl_xor_sync(0xffffffffu, q1, 2);
            if ((lane & 3) == 0) {
                atomicAdd(&stS[r0], (double)s0);
                atomicAdd(&stQ[r0], (double)q0);
                atomicAdd(&stS[r0 + 8], (double)s1);
                atomicAdd(&stQ[r0 + 8], (double)q1);
            }
        }
    }
}

template <int BIAS, bool RES, bool STATS, typename OutT>
static void launch_tn(const __half* A, ll sA, ll sA2, int lda,
                      const __half* Bg, ll sB, ll sB2, int ldb,
                      OutT* Cm, ll sC, ll sC2, int ldc,
                      int Md, int Nd, int Kd,
                      const float* bias, int biasStr,
                      const __half* R, ll sR, int ldr,
                      float scale, int batch, double* stS, double* stQ) {
    cudaFuncSetAttribute(gemm_tn<BIAS, RES, STATS, OutT>,
                         cudaFuncAttributeMaxDynamicSharedMemorySize, 65536);
    dim3 grid(Nd / 128, Md / 128, batch);
    gemm_tn<BIAS, RES, STATS, OutT><<<grid, 256, 65536>>>(
        A, sA, sA2, lda, Bg, sB, sB2, ldb, Cm, sC, sC2, ldc, Kd,
        bias, biasStr, R, sR, ldr, scale, stS, stQ);
}

// ---------------- driver ----------------
extern "C" void kernel_launch(void* const* d_in, const int* in_sizes, int n_in,
                              void* d_out, int out_size) {
    const float* x = (const float*)d_in[0];
    int pb = (n_in > 1 && in_sizes[1] == 1) ? 2 : 1;
    const float* P[20];
    for (int i = 0; i < 20; i++) P[i] = (const float*)d_in[pb + i];
    float* out = (float*)d_out;

    __half *xTh, *ctxh, *Qh, *Kh, *Vth, *Sh, *Yh, *Zh, *Ph, *Wh;
    float *bp;
    double *stS, *stQ;
    cudaGetSymbolAddress((void**)&xTh, g_xTh);
    cudaGetSymbolAddress((void**)&ctxh, g_ctxh);
    cudaGetSymbolAddress((void**)&Qh, g_Qh);
    cudaGetSymbolAddress((void**)&Kh, g_Kh);
    cudaGetSymbolAddress((void**)&Vth, g_Vth);
    cudaGetSymbolAddress((void**)&Sh, g_Sh);
    cudaGetSymbolAddress((void**)&Yh, g_Yh);
    cudaGetSymbolAddress((void**)&Zh, g_Zh);
    cudaGetSymbolAddress((void**)&Ph, g_Ph);
    cudaGetSymbolAddress((void**)&Wh, g_Wh);
    cudaGetSymbolAddress((void**)&bp, g_bp);
    cudaGetSymbolAddress((void**)&stS, g_sum);
    cudaGetSymbolAddress((void**)&stQ, g_sumsq);

    const int CC = C_ * C_;

    // selection + packing
    transpose_kernel<<<dim3(N_ / 32, C_ / 32, B_), dim3(32, 8)>>>(x);
    mean_kernel<<<dim3(C_, B_), 256>>>(x);
    score_kernel<<<dim3(N_ / 256, B_), 256>>>(x);
    sort_kernel<<<B_, 1024>>>();
    gather_kernel<<<dim3(M_ / 8, B_, 2), 256>>>();
    pack_w<<<2560, 256>>>(P[0], P[8], P[2], P[10], P[4], P[12], P[6], P[14], P[16]);
    pack_b<<<8, 256>>>(P[1], P[9], P[3], P[11], P[5], P[13], P[7], P[15]);
    bn_zero<<<1, 256>>>();

    // Q both sides in one GEMM: [b][n][512] = xTh · [Wq_s;Wq_g]^T + bq2
    launch_tn<1, false, false>(xTh, (ll)N_ * C_, 0, C_,
                               Wh, 0, 0, C_,
                               Qh, (ll)N_ * 2 * C_, 0, 2 * C_,
                               N_, 2 * C_, C_, bp, 0,
                               (const __half*)nullptr, 0, 0, 1.f, B_, nullptr, nullptr);
    // K: z=32 (side|b)
    launch_tn<1, false, false>(ctxh, (ll)M_ * C_, (ll)B_ * M_ * C_, C_,
                               Wh + 2 * CC, 0, CC, C_,
                               Kh, (ll)M_ * C_, (ll)B_ * M_ * C_, C_,
                               M_, C_, C_, bp + 512, 256,
                               (const __half*)nullptr, 0, 0, 1.f, 2 * B_, nullptr, nullptr);
    // V^T: [side][b][d][m] = Wv · ctx^T + bv (per-row bias)
    launch_tn<2, false, false>(Wh + 4 * CC, 0, CC, C_,
                               ctxh, (ll)M_ * C_, (ll)B_ * M_ * C_, C_,
                               Vth, (ll)C_ * M_, (ll)B_ * C_ * M_, M_,
                               C_, M_, C_, bp + 1024, 256,
                               (const __half*)nullptr, 0, 0, 1.f, 2 * B_, nullptr, nullptr);
    // S = Q·K^T / 16
    launch_tn<0, false, false>(Qh, (ll)N_ * 2 * C_, (ll)C_, 2 * C_,
                               Kh, (ll)M_ * C_, (ll)B_ * M_ * C_, C_,
                               Sh, (ll)N_ * M_, (ll)B_ * N_ * M_, M_,
                               N_, M_, C_, nullptr, 0,
                               (const __half*)nullptr, 0, 0, 1.f / 16.f, 2 * B_, nullptr, nullptr);
    softmax_kernel<<<dim3(N_, 2 * B_), 256>>>();
    // Y = P·V
    launch_tn<0, false, false>(Sh, (ll)N_ * M_, (ll)B_ * N_ * M_, M_,
                               Vth, (ll)C_ * M_, (ll)B_ * C_ * M_, M_,
                               Yh, (ll)N_ * C_, (ll)B_ * N_ * C_, C_,
                               N_, C_, M_, nullptr, 0,
                               (const __half*)nullptr, 0, 0, 1.f, 2 * B_, nullptr, nullptr);
    // Z (concat slot) = Y·Wo^T + bo + x
    launch_tn<1, true, false>(Yh, (ll)N_ * C_, (ll)B_ * N_ * C_, C_,
                              Wh + 6 * CC, 0, CC, C_,
                              Zh, (ll)N_ * 2 * C_, (ll)C_, 2 * C_,
                              N_, C_, C_, bp + 1536, 256,
                              xTh, (ll)N_ * C_, C_, 1.f, 2 * B_, nullptr, nullptr);
    // fuse conv -> fp16 pre-BN + fused stats
    launch_tn<2, false, true>(Wh + 8 * CC, 0, 0, 2 * C_,
                              Zh, (ll)N_ * 2 * C_, 0, 2 * C_,
                              Ph, (ll)C_ * N_, 0, N_,
                              C_, N_, 2 * C_, P[17], 0,
                              (const __half*)nullptr, 0, 0, 1.f, B_, stS, stQ);

    bn_finalize<<<1, 256>>>(P[18], P[19]);
    bn_final<<<dim3(N_ / 256, C_, B_), 256>>>(out);
}

// round 8
// speedup vs baseline: 1.5396x; 1.2836x over previous
#include <cuda_runtime.h>
#include <cuda_fp16.h>
#include <cstdint>

#define B_ 16
#define C_ 256
#define N_ 4096
#define M_ 1024
#define EPS_ 1e-5f
typedef long long ll;

// ---------------- scratch ----------------
__device__ float g_xm[B_ * C_];
__device__ float g_score[B_ * N_];
__device__ int   g_idx[2 * B_ * M_];
__device__ double g_sum[C_];
__device__ double g_sumsq[C_];
__device__ float g_bnw[C_];
__device__ float g_bnb[C_];
__device__ float g_bp[3 * 512];          // packed biases: bq2|bk2|bv2
__device__ float g_bc[C_];               // bconst for final gemm
__device__ float g_l[2 * B_ * N_];       // softmax row sums

__device__ __half g_cat[(ll)B_ * N_ * 768];   // [b][n][ Y_s(256) | Y_g(256) | x(256) ]
__device__ __half g_ctxh[2LL * B_ * M_ * C_]; // [side][b][m][c]
__device__ __half g_Qh[(ll)B_ * N_ * 512];    // [b][n][512]
__device__ __half g_Kh[2LL * B_ * M_ * C_];
__device__ __half g_Vth[2LL * B_ * C_ * M_];  // [side][b][d][m]
__device__ __half g_Sh[2LL * B_ * N_ * M_];   // unnormalized exp scores
__device__ __half g_Ph[(ll)B_ * C_ * N_];     // pre-BN output
__device__ __half g_Wh[6 * C_ * C_];          // Wq_s,Wq_g,Wk_s,Wk_g,Wv_s,Wv_g
__device__ __half g_W3[C_ * 768];             // [Wc_s | Wc_g | Wx]

// ---------------- PTX ----------------
__device__ __forceinline__ void cp16(uint32_t dst, const void* src) {
    asm volatile("cp.async.cg.shared.global [%0], [%1], 16;" :: "r"(dst), "l"(src));
}
__device__ __forceinline__ void cp_commit() { asm volatile("cp.async.commit_group;"); }
template <int Nw> __device__ __forceinline__ void cp_wait() {
    asm volatile("cp.async.wait_group %0;" :: "n"(Nw));
}
__device__ __forceinline__ void ldsm_x4(uint32_t* r, uint32_t a) {
    asm volatile("ldmatrix.sync.aligned.m8n8.x4.shared.b16 {%0,%1,%2,%3}, [%4];"
        : "=r"(r[0]), "=r"(r[1]), "=r"(r[2]), "=r"(r[3]) : "r"(a));
}
__device__ __forceinline__ void ldsm_x2(uint32_t* r, uint32_t a) {
    asm volatile("ldmatrix.sync.aligned.m8n8.x2.shared.b16 {%0,%1}, [%2];"
        : "=r"(r[0]), "=r"(r[1]) : "r"(a));
}
__device__ __forceinline__ void mma_f16(float* c, const uint32_t* a, const uint32_t* b) {
    asm volatile("mma.sync.aligned.m16n8k16.row.col.f32.f16.f16.f32 "
        "{%0,%1,%2,%3}, {%4,%5,%6,%7}, {%8,%9}, {%0,%1,%2,%3};"
        : "+f"(c[0]), "+f"(c[1]), "+f"(c[2]), "+f"(c[3])
        : "r"(a[0]), "r"(a[1]), "r"(a[2]), "r"(a[3]), "r"(b[0]), "r"(b[1]));
}

// ---------------- small kernels ----------------
__global__ void transpose_kernel(const float* __restrict__ x) {
    __shared__ float t[32][33];
    int b = blockIdx.z, n0 = blockIdx.x * 32, c0 = blockIdx.y * 32;
    int tx = threadIdx.x, ty = threadIdx.y;
    const float* xp = x + (ll)b * C_ * N_;
    __half* xhp = g_cat + (ll)b * N_ * 768 + 512;
#pragma unroll
    for (int i = 0; i < 32; i += 8)
        t[ty + i][tx] = xp[(ll)(c0 + ty + i) * N_ + n0 + tx];
    __syncthreads();
#pragma unroll
    for (int i = 0; i < 32; i += 8)
        xhp[(ll)(n0 + ty + i) * 768 + c0 + tx] = __float2half_rn(t[tx][ty + i]);
}

__global__ void mean_kernel(const float* __restrict__ x) {
    int c = blockIdx.x, b = blockIdx.y, t = threadIdx.x;
    const float* p = x + ((ll)b * C_ + c) * N_;
    float s = 0.f;
    for (int i = t; i < N_; i += 256) s += p[i];
    __shared__ float sh[256];
    sh[t] = s; __syncthreads();
    for (int w = 128; w > 0; w >>= 1) { if (t < w) sh[t] += sh[t + w]; __syncthreads(); }
    if (t == 0) g_xm[b * C_ + c] = sh[0] * (1.0f / N_);
}

__global__ void score_kernel(const float* __restrict__ x) {
    int n = blockIdx.x * 256 + threadIdx.x;
    int b = blockIdx.y;
    const float* px = x + (ll)b * C_ * N_;
    const float* pm = g_xm + b * C_;
    float s = 0.f;
#pragma unroll 8
    for (int c = 0; c < C_; c++) {
        float d = px[(ll)c * N_ + n] - pm[c];
        s += d * d;
    }
    g_score[b * N_ + n] = s;
}

__global__ void sort_kernel() {
    __shared__ float sv[N_];
    __shared__ int   si[N_];
    int b = blockIdx.x, t = threadIdx.x;
    for (int i = t; i < N_; i += 1024) { sv[i] = g_score[b * N_ + i]; si[i] = i; }
    __syncthreads();
    for (int k = 2; k <= N_; k <<= 1)
        for (int j = k >> 1; j > 0; j >>= 1) {
            for (int i = t; i < N_; i += 1024) {
                int ixj = i ^ j;
                if (ixj > i) {
                    bool desc = ((i & k) == 0);
                    float a = sv[i], c = sv[ixj];
                    if (desc ? (a < c) : (a > c)) {
                        sv[i] = c; sv[ixj] = a;
                        int ta = si[i]; si[i] = si[ixj]; si[ixj] = ta;
                    }
                }
            }
            __syncthreads();
        }
    for (int m = t; m < M_; m += 1024) {
        g_idx[0 * B_ * M_ + b * M_ + m] = si[m];
        g_idx[1 * B_ * M_ + b * M_ + m] = si[N_ - M_ + m];
    }
}

__global__ void gather_kernel() {
    int side = blockIdx.z, b = blockIdx.y;
    int m = blockIdx.x * 8 + (threadIdx.x >> 5);
    int c8 = threadIdx.x & 31;
    int j = g_idx[side * B_ * M_ + b * M_ + m];
    uint4 v = ((const uint4*)(g_cat + ((ll)b * N_ + j) * 768 + 512))[c8];
    ((uint4*)(g_ctxh + (((ll)side * B_ + b) * M_ + m) * C_))[c8] = v;
}

__global__ void pack_w(const float* a0, const float* a1, const float* a2,
                       const float* a3, const float* a4, const float* a5) {
    int i = blockIdx.x * 256 + threadIdx.x;  // 393216 total
    const float* p[6] = {a0, a1, a2, a3, a4, a5};
    g_Wh[i] = __float2half_rn(p[i >> 16][i & 65535]);
}

__global__ void pack_b(const float* b0, const float* b1, const float* b2,
                       const float* b3, const float* b4, const float* b5) {
    int i = threadIdx.x + blockIdx.x * 256;  // 1536
    const float* p[6] = {b0, b1, b2, b3, b4, b5};
    int grp = i >> 9, k = i & 511;
    g_bp[i] = p[(grp << 1) | (k >> 8)][k & 255];
}

// W3[d][0:256]=Wf_s@Wo_s, [256:512]=Wf_g@Wo_g, [512:768]=Wf_s+Wf_g; bconst.
__global__ void combine_w(const float* __restrict__ Wf,
                          const float* __restrict__ Wo_s, const float* __restrict__ Wo_g,
                          const float* __restrict__ bf,
                          const float* __restrict__ bo_s, const float* __restrict__ bo_g) {
    int d = blockIdx.x, t = threadIdx.x;  // 256 x 256
    __shared__ float wf[512];
    wf[t] = Wf[d * 512 + t];
    wf[t + 256] = Wf[d * 512 + 256 + t];
    __syncthreads();
    float a0 = 0.f, a1 = 0.f;
#pragma unroll 4
    for (int e = 0; e < 256; e++) {
        a0 += wf[e] * Wo_s[e * 256 + t];
        a1 += wf[256 + e] * Wo_g[e * 256 + t];
    }
    g_W3[d * 768 + t] = __float2half_rn(a0);
    g_W3[d * 768 + 256 + t] = __float2half_rn(a1);
    g_W3[d * 768 + 512 + t] = __float2half_rn(wf[t] + wf[256 + t]);
    if (t == 0) {
        float bc = bf[d];
        for (int e = 0; e < 256; e++) bc += wf[e] * bo_s[e] + wf[256 + e] * bo_g[e];
        g_bc[d] = bc;
    }
}

__global__ void zero_kernel() {
    int i = blockIdx.x * 256 + threadIdx.x;
    if (i < 2 * B_ * N_) g_l[i] = 0.f;
    if (i < C_) { g_sum[i] = 0.0; g_sumsq[i] = 0.0; }
}

__global__ void bn_finalize(const float* __restrict__ gamma, const float* __restrict__ beta) {
    int d = threadIdx.x;
    double cnt = (double)B_ * N_;
    double mu = g_sum[d] / cnt;
    double var = g_sumsq[d] / cnt - mu * mu;
    float w = gamma[d] * rsqrtf((float)var + EPS_);
    g_bnw[d] = w;
    g_bnb[d] = beta[d] - (float)mu * w;
}

__global__ void bn_final(float* __restrict__ out) {
    int n = blockIdx.x * 256 + threadIdx.x;
    int d = blockIdx.y, b = blockIdx.z;
    ll o = ((ll)b * C_ + d) * N_ + n;
    float v = __half2float(g_Ph[o]) * g_bnw[d] + g_bnb[d];
    out[o] = v > 0.f ? v : 0.f;
}

// ---------------- fp16 TN GEMM (R4 core; EPI: 0 none, 1 exp+rowsum, 2 div-by-l) ----------------
template <int BIAS, int EPI, bool STATS>
__global__ __launch_bounds__(256, 2)
void gemm_tn(const __half* __restrict__ A, ll sA, ll sA2, int lda,
             const __half* __restrict__ Bg, ll sB, ll sB2, int ldb,
             __half* __restrict__ Cm, ll sC, ll sC2, int ldc, int Kd,
             const float* __restrict__ bias, int biasStr,
             float scale, double* stS, double* stQ,
             float* lrow, ll sL) {
    extern __shared__ char smc[];
    const uint32_t smu = (uint32_t)__cvta_generic_to_shared(smc);
    const int bz = blockIdx.z, side = bz >> 4, b = bz & 15;
    A += (ll)b * sA + (ll)side * sA2;
    Bg += (ll)b * sB + (ll)side * sB2;
    Cm += (ll)b * sC + (ll)side * sC2;
    if (BIAS) bias += side * biasStr;
    if (EPI) lrow += (ll)bz * sL;
    const int row0 = blockIdx.y * 128, col0 = blockIdx.x * 128;
    const int tid = threadIdx.x, lane = tid & 31, warp = tid >> 5;
    const int wm = warp >> 2, wn = warp & 3;
    const int rA = lane & 15, selA = lane >> 4;
    const int tb = lane & 15, rB = tb & 7, midB = tb >> 3;

    float acc[4][4][4];
#pragma unroll
    for (int i = 0; i < 4; i++)
#pragma unroll
        for (int j = 0; j < 4; j++)
#pragma unroll
            for (int q = 0; q < 4; q++) acc[i][j][q] = 0.f;

    const int nT = Kd / 64;
#pragma unroll
    for (int r = 0; r < 4; r++) {
        int lin = tid + r * 256;
        int row = lin >> 3, f4 = lin & 7;
        uint32_t so = (uint32_t)((row * 8 + (f4 ^ (row & 7))) * 16);
        cp16(smu + so, A + (ll)(row0 + row) * lda + f4 * 8);
        cp16(smu + 16384 + so, Bg + (ll)(col0 + row) * ldb + f4 * 8);
    }
    cp_commit();

    for (int t = 0; t < nT; t++) {
        if (t + 1 < nT) {
            int st = (t + 1) & 1, k0 = (t + 1) * 64;
#pragma unroll
            for (int r = 0; r < 4; r++) {
                int lin = tid + r * 256;
                int row = lin >> 3, f4 = lin & 7;
                uint32_t so = (uint32_t)(st * 32768 + (row * 8 + (f4 ^ (row & 7))) * 16);
                cp16(smu + so, A + (ll)(row0 + row) * lda + k0 + f4 * 8);
                cp16(smu + 16384 + so, Bg + (ll)(col0 + row) * ldb + k0 + f4 * 8);
            }
            cp_commit(); cp_wait<1>();
        } else cp_wait<0>();
        __syncthreads();

        uint32_t Au = smu + (uint32_t)((t & 1) * 32768);
        uint32_t Bu = Au + 16384;
#pragma unroll
        for (int kt = 0; kt < 4; kt++) {
            uint32_t af[4][4], bf4[4][2];
#pragma unroll
            for (int mt = 0; mt < 4; mt++) {
                int row = wm * 64 + mt * 16 + rA;
                int u = kt * 2 + selA;
                ldsm_x4(af[mt], Au + (uint32_t)((row * 8 + (u ^ (row & 7))) * 16));
            }
#pragma unroll
            for (int nt = 0; nt < 4; nt++) {
                int row = wn * 32 + nt * 8 + rB;
                int u = kt * 2 + midB;
                ldsm_x2(bf4[nt], Bu + (uint32_t)((row * 8 + (u ^ (row & 7))) * 16));
            }
#pragma unroll
            for (int mt = 0; mt < 4; mt++)
#pragma unroll
                for (int nt = 0; nt < 4; nt++)
                    mma_f16(acc[mt][nt], af[mt], bf4[nt]);
        }
        __syncthreads();
    }

    const int gr = lane >> 2, gc = (lane & 3) * 2;
#pragma unroll
    for (int mt = 0; mt < 4; mt++) {
        int r0 = row0 + wm * 64 + mt * 16 + gr;
        float inv0 = 1.f, inv1 = 1.f;
        if (EPI == 2) { inv0 = 1.f / lrow[r0]; inv1 = 1.f / lrow[r0 + 8]; }
        float s0 = 0.f, q0 = 0.f, s1 = 0.f, q1 = 0.f;
#pragma unroll
        for (int nt = 0; nt < 4; nt++) {
            int col = col0 + wn * 32 + nt * 8 + gc;
            float v0x = acc[mt][nt][0] * scale, v0y = acc[mt][nt][1] * scale;
            float v1x = acc[mt][nt][2] * scale, v1y = acc[mt][nt][3] * scale;
            if (BIAS == 1) {
                float bx = bias[col], by = bias[col + 1];
                v0x += bx; v0y += by; v1x += bx; v1y += by;
            } else if (BIAS == 2) {
                float b0v = bias[r0], b1v = bias[r0 + 8];
                v0x += b0v; v0y += b0v; v1x += b1v; v1y += b1v;
            }
            if (EPI == 1) {
                v0x = __expf(v0x); v0y = __expf(v0y);
                v1x = __expf(v1x); v1y = __expf(v1y);
                s0 += v0x + v0y; s1 += v1x + v1y;
            }
            if (EPI == 2) { v0x *= inv0; v0y *= inv0; v1x *= inv1; v1y *= inv1; }
            if (STATS) {
                s0 += v0x + v0y; q0 += v0x * v0x + v0y * v0y;
                s1 += v1x + v1y; q1 += v1x * v1x + v1y * v1y;
            }
            *(__half2*)(Cm + (ll)r0 * ldc + col) = __floats2half2_rn(v0x, v0y);
            *(__half2*)(Cm + (ll)(r0 + 8) * ldc + col) = __floats2half2_rn(v1x, v1y);
        }
        if (EPI == 1) {
            s0 += __shfl_xor_sync(0xffffffffu, s0, 1); s0 += __shfl_xor_sync(0xffffffffu, s0, 2);
            s1 += __shfl_xor_sync(0xffffffffu, s1, 1); s1 += __shfl_xor_sync(0xffffffffu, s1, 2);
            if ((lane & 3) == 0) {
                atomicAdd(&lrow[r0], s0);
                atomicAdd(&lrow[r0 + 8], s1);
            }
        }
        if (STATS) {
            s0 += __shfl_xor_sync(0xffffffffu, s0, 1); s0 += __shfl_xor_sync(0xffffffffu, s0, 2);
            q0 += __shfl_xor_sync(0xffffffffu, q0, 1); q0 += __shfl_xor_sync(0xffffffffu, q0, 2);
            s1 += __shfl_xor_sync(0xffffffffu, s1, 1); s1 += __shfl_xor_sync(0xffffffffu, s1, 2);
            q1 += __shfl_xor_sync(0xffffffffu, q1, 1); q1 += __shfl_xor_sync(0xffffffffu, q1, 2);
            if ((lane & 3) == 0) {
                atomicAdd(&stS[r0], (double)s0);
                atomicAdd(&stQ[r0], (double)q0);
                atomicAdd(&stS[r0 + 8], (double)s1);
                atomicAdd(&stQ[r0 + 8], (double)q1);
            }
        }
    }
}

template <int BIAS, int EPI, bool STATS>
static void launch_tn(const __half* A, ll sA, ll sA2, int lda,
                      const __half* Bg, ll sB, ll sB2, int ldb,
                      __half* Cm, ll sC, ll sC2, int ldc,
                      int Md, int Nd, int Kd,
                      const float* bias, int biasStr,
                      float scale, int batch,
                      double* stS, double* stQ, float* lrow, ll sL) {
    cudaFuncSetAttribute(gemm_tn<BIAS, EPI, STATS>,
                         cudaFuncAttributeMaxDynamicSharedMemorySize, 65536);
    dim3 grid(Nd / 128, Md / 128, batch);
    gemm_tn<BIAS, EPI, STATS><<<grid, 256, 65536>>>(
        A, sA, sA2, lda, Bg, sB, sB2, ldb, Cm, sC, sC2, ldc, Kd,
        bias, biasStr, scale, stS, stQ, lrow, sL);
}

// ---------------- driver ----------------
extern "C" void kernel_launch(void* const* d_in, const int* in_sizes, int n_in,
                              void* d_out, int out_size) {
    const float* x = (const float*)d_in[0];
    int pb = (n_in > 1 && in_sizes[1] == 1) ? 2 : 1;
    const float* P[20];
    for (int i = 0; i < 20; i++) P[i] = (const float*)d_in[pb + i];
    float* out = (float*)d_out;

    __half *cat, *ctxh, *Qh, *Kh, *Vth, *Sh, *Ph, *Wh, *W3;
    float *bp, *bc, *lptr;
    double *stS, *stQ;
    cudaGetSymbolAddress((void**)&cat, g_cat);
    cudaGetSymbolAddress((void**)&ctxh, g_ctxh);
    cudaGetSymbolAddress((void**)&Qh, g_Qh);
    cudaGetSymbolAddress((void**)&Kh, g_Kh);
    cudaGetSymbolAddress((void**)&Vth, g_Vth);
    cudaGetSymbolAddress((void**)&Sh, g_Sh);
    cudaGetSymbolAddress((void**)&Ph, g_Ph);
    cudaGetSymbolAddress((void**)&Wh, g_Wh);
    cudaGetSymbolAddress((void**)&W3, g_W3);
    cudaGetSymbolAddress((void**)&bp, g_bp);
    cudaGetSymbolAddress((void**)&bc, g_bc);
    cudaGetSymbolAddress((void**)&lptr, g_l);
    cudaGetSymbolAddress((void**)&stS, g_sum);
    cudaGetSymbolAddress((void**)&stQ, g_sumsq);

    const int CC = C_ * C_;

    transpose_kernel<<<dim3(N_ / 32, C_ / 32, B_), dim3(32, 8)>>>(x);
    mean_kernel<<<dim3(C_, B_), 256>>>(x);
    score_kernel<<<dim3(N_ / 256, B_), 256>>>(x);
    sort_kernel<<<B_, 1024>>>();
    gather_kernel<<<dim3(M_ / 8, B_, 2), 256>>>();
    pack_w<<<1536, 256>>>(P[0], P[8], P[2], P[10], P[4], P[12]);
    pack_b<<<6, 256>>>(P[1], P[9], P[3], P[11], P[5], P[13]);
    combine_w<<<256, 256>>>(P[16], P[6], P[14], P[17], P[7], P[15]);
    zero_kernel<<<512, 256>>>();

    // Q (both sides): [b][n][512] = cat_x · [Wq_s;Wq_g]^T + bq2
    launch_tn<1, 0, false>(cat + 512, (ll)N_ * 768, 0, 768,
                           Wh, 0, 0, C_,
                           Qh, (ll)N_ * 512, 0, 512,
                           N_, 512, C_, bp, 0, 1.f, B_, nullptr, nullptr, nullptr, 0);
    // K: z=32
    launch_tn<1, 0, false>(ctxh, (ll)M_ * C_, (ll)B_ * M_ * C_, C_,
                           Wh + 2 * CC, 0, CC, C_,
                           Kh, (ll)M_ * C_, (ll)B_ * M_ * C_, C_,
                           M_, C_, C_, bp + 512, 256, 1.f, 2 * B_, nullptr, nullptr, nullptr, 0);
    // V^T: [side][b][d][m]
    launch_tn<2, 0, false>(Wh + 4 * CC, 0, CC, C_,
                           ctxh, (ll)M_ * C_, (ll)B_ * M_ * C_, C_,
                           Vth, (ll)C_ * M_, (ll)B_ * C_ * M_, M_,
                           C_, M_, C_, bp + 1024, 256, 1.f, 2 * B_, nullptr, nullptr, nullptr, 0);
    // S̃ = exp(Q·K^T / 16), row sums into g_l
    launch_tn<0, 1, false>(Qh, (ll)N_ * 512, (ll)C_, 512,
                           Kh, (ll)M_ * C_, (ll)B_ * M_ * C_, C_,
                           Sh, (ll)N_ * M_, (ll)B_ * N_ * M_, M_,
                           N_, M_, C_, nullptr, 0, 1.f / 16.f, 2 * B_,
                           nullptr, nullptr, lptr, N_);
    // Y = (S̃·V) / l  -> cat[:, side*256 : side*256+256]
    launch_tn<0, 2, false>(Sh, (ll)N_ * M_, (ll)B_ * N_ * M_, M_,
                           Vth, (ll)C_ * M_, (ll)B_ * C_ * M_, M_,
                           cat, (ll)N_ * 768, 256, 768,
                           N_, C_, M_, nullptr, 0, 1.f, 2 * B_,
                           nullptr, nullptr, lptr, N_);
    // out_pre[b][d][n] = W3 · cat[n,:] + bconst, fused BN stats
    launch_tn<2, 0, true>(W3, 0, 0, 768,
                          cat, (ll)N_ * 768, 0, 768,
                          Ph, (ll)C_ * N_, 0, N_,
                          C_, N_, 768, bc, 0, 1.f, B_, stS, stQ, nullptr, 0);

    bn_finalize<<<1, 256>>>(P[18], P[19]);
    bn_final<<<dim3(N_ / 256, C_, B_), 256>>>(out);
}

// round 9
// speedup vs baseline: 1.5720x; 1.0210x over previous
#include <cuda_runtime.h>
#include <cuda_fp16.h>
#include <cstdint>

#define B_ 16
#define C_ 256
#define N_ 4096
#define M_ 1024
#define EPS_ 1e-5f
typedef long long ll;

// ---------------- scratch ----------------
__device__ float g_xm[B_ * C_];
__device__ float g_score[B_ * N_];
__device__ int   g_idx[2 * B_ * M_];
__device__ double g_sum[C_];
__device__ double g_sumsq[C_];
__device__ float g_bnw[C_];
__device__ float g_bnb[C_];
__device__ float g_bp[3 * 512];          // packed biases: bq2|bk2|bv2
__device__ float g_bc[C_];               // bconst for final gemm
__device__ float g_l[2 * B_ * N_];       // softmax row sums

__device__ __half g_cat[(ll)B_ * N_ * 768];   // [b][n][ Y_s(256) | Y_g(256) | x(256) ]
__device__ __half g_ctxh[2LL * B_ * M_ * C_]; // [side][b][m][c]
__device__ __half g_Qh[(ll)B_ * N_ * 512];    // [b][n][512]
__device__ __half g_Kh[2LL * B_ * M_ * C_];
__device__ __half g_Vth[2LL * B_ * C_ * M_];  // [side][b][d][m]
__device__ __half g_Sh[2LL * B_ * N_ * M_];   // unnormalized exp scores
__device__ __half g_Ph[(ll)B_ * C_ * N_];     // pre-BN output
__device__ __half g_Wh[6 * C_ * C_];          // Wq_s,Wq_g,Wk_s,Wk_g,Wv_s,Wv_g
__device__ __half g_W3[C_ * 768];             // [Wc_s | Wc_g | Wx]

// ---------------- PTX ----------------
__device__ __forceinline__ void cp16(uint32_t dst, const void* src) {
    asm volatile("cp.async.cg.shared.global [%0], [%1], 16;" :: "r"(dst), "l"(src));
}
__device__ __forceinline__ void cp_commit() { asm volatile("cp.async.commit_group;"); }
template <int Nw> __device__ __forceinline__ void cp_wait() {
    asm volatile("cp.async.wait_group %0;" :: "n"(Nw));
}
__device__ __forceinline__ void ldsm_x4(uint32_t* r, uint32_t a) {
    asm volatile("ldmatrix.sync.aligned.m8n8.x4.shared.b16 {%0,%1,%2,%3}, [%4];"
        : "=r"(r[0]), "=r"(r[1]), "=r"(r[2]), "=r"(r[3]) : "r"(a));
}
__device__ __forceinline__ void ldsm_x2(uint32_t* r, uint32_t a) {
    asm volatile("ldmatrix.sync.aligned.m8n8.x2.shared.b16 {%0,%1}, [%2];"
        : "=r"(r[0]), "=r"(r[1]) : "r"(a));
}
__device__ __forceinline__ void mma_f16(float* c, const uint32_t* a, const uint32_t* b) {
    asm volatile("mma.sync.aligned.m16n8k16.row.col.f32.f16.f16.f32 "
        "{%0,%1,%2,%3}, {%4,%5,%6,%7}, {%8,%9}, {%0,%1,%2,%3};"
        : "+f"(c[0]), "+f"(c[1]), "+f"(c[2]), "+f"(c[3])
        : "r"(a[0]), "r"(a[1]), "r"(a[2]), "r"(a[3]), "r"(b[0]), "r"(b[1]));
}
__device__ __forceinline__ uint32_t ex2_h2(uint32_t u) {
    asm("ex2.approx.f16x2 %0, %0;" : "+r"(u));
    return u;
}

// ---------------- small kernels ----------------
__global__ void transpose_kernel(const float* __restrict__ x) {
    __shared__ float t[32][33];
    int b = blockIdx.z, n0 = blockIdx.x * 32, c0 = blockIdx.y * 32;
    int tx = threadIdx.x, ty = threadIdx.y;
    const float* xp = x + (ll)b * C_ * N_;
    __half* xhp = g_cat + (ll)b * N_ * 768 + 512;
#pragma unroll
    for (int i = 0; i < 32; i += 8)
        t[ty + i][tx] = xp[(ll)(c0 + ty + i) * N_ + n0 + tx];
    __syncthreads();
#pragma unroll
    for (int i = 0; i < 32; i += 8)
        xhp[(ll)(n0 + ty + i) * 768 + c0 + tx] = __float2half_rn(t[tx][ty + i]);
}

__global__ void mean_kernel(const float* __restrict__ x) {
    int c = blockIdx.x, b = blockIdx.y, t = threadIdx.x;
    const float* p = x + ((ll)b * C_ + c) * N_;
    float s = 0.f;
    for (int i = t; i < N_; i += 256) s += p[i];
    __shared__ float sh[256];
    sh[t] = s; __syncthreads();
    for (int w = 128; w > 0; w >>= 1) { if (t < w) sh[t] += sh[t + w]; __syncthreads(); }
    if (t == 0) g_xm[b * C_ + c] = sh[0] * (1.0f / N_);
}

__global__ void score_kernel(const float* __restrict__ x) {
    int n = blockIdx.x * 256 + threadIdx.x;
    int b = blockIdx.y;
    const float* px = x + (ll)b * C_ * N_;
    const float* pm = g_xm + b * C_;
    float s = 0.f;
#pragma unroll 8
    for (int c = 0; c < C_; c++) {
        float d = px[(ll)c * N_ + n] - pm[c];
        s += d * d;
    }
    g_score[b * N_ + n] = s;
}

__global__ void sort_kernel() {
    __shared__ float sv[N_];
    __shared__ int   si[N_];
    int b = blockIdx.x, t = threadIdx.x;
    for (int i = t; i < N_; i += 1024) { sv[i] = g_score[b * N_ + i]; si[i] = i; }
    __syncthreads();
    for (int k = 2; k <= N_; k <<= 1)
        for (int j = k >> 1; j > 0; j >>= 1) {
            for (int i = t; i < N_; i += 1024) {
                int ixj = i ^ j;
                if (ixj > i) {
                    bool desc = ((i & k) == 0);
                    float a = sv[i], c = sv[ixj];
                    if (desc ? (a < c) : (a > c)) {
                        sv[i] = c; sv[ixj] = a;
                        int ta = si[i]; si[i] = si[ixj]; si[ixj] = ta;
                    }
                }
            }
            __syncthreads();
        }
    for (int m = t; m < M_; m += 1024) {
        g_idx[0 * B_ * M_ + b * M_ + m] = si[m];
        g_idx[1 * B_ * M_ + b * M_ + m] = si[N_ - M_ + m];
    }
}

__global__ void gather_kernel() {
    int side = blockIdx.z, b = blockIdx.y;
    int m = blockIdx.x * 8 + (threadIdx.x >> 5);
    int c8 = threadIdx.x & 31;
    int j = g_idx[side * B_ * M_ + b * M_ + m];
    uint4 v = ((const uint4*)(g_cat + ((ll)b * N_ + j) * 768 + 512))[c8];
    ((uint4*)(g_ctxh + (((ll)side * B_ + b) * M_ + m) * C_))[c8] = v;
}

__global__ void pack_w(const float* a0, const float* a1, const float* a2,
                       const float* a3, const float* a4, const float* a5) {
    int i = blockIdx.x * 256 + threadIdx.x;
    const float* p[6] = {a0, a1, a2, a3, a4, a5};
    g_Wh[i] = __float2half_rn(p[i >> 16][i & 65535]);
}

__global__ void pack_b(const float* b0, const float* b1, const float* b2,
                       const float* b3, const float* b4, const float* b5) {
    int i = threadIdx.x + blockIdx.x * 256;
    const float* p[6] = {b0, b1, b2, b3, b4, b5};
    int grp = i >> 9, k = i & 511;
    g_bp[i] = p[(grp << 1) | (k >> 8)][k & 255];
}

__global__ void combine_w(const float* __restrict__ Wf,
                          const float* __restrict__ Wo_s, const float* __restrict__ Wo_g,
                          const float* __restrict__ bf,
                          const float* __restrict__ bo_s, const float* __restrict__ bo_g) {
    int d = blockIdx.x, t = threadIdx.x;
    __shared__ float wf[512];
    wf[t] = Wf[d * 512 + t];
    wf[t + 256] = Wf[d * 512 + 256 + t];
    __syncthreads();
    float a0 = 0.f, a1 = 0.f;
#pragma unroll 4
    for (int e = 0; e < 256; e++) {
        a0 += wf[e] * Wo_s[e * 256 + t];
        a1 += wf[256 + e] * Wo_g[e * 256 + t];
    }
    g_W3[d * 768 + t] = __float2half_rn(a0);
    g_W3[d * 768 + 256 + t] = __float2half_rn(a1);
    g_W3[d * 768 + 512 + t] = __float2half_rn(wf[t] + wf[256 + t]);
    if (t == 0) {
        float bc = bf[d];
        for (int e = 0; e < 256; e++) bc += wf[e] * bo_s[e] + wf[256 + e] * bo_g[e];
        g_bc[d] = bc;
    }
}

__global__ void zero_kernel() {
    int i = blockIdx.x * 256 + threadIdx.x;
    if (i < 2 * B_ * N_) g_l[i] = 0.f;
    if (i < C_) { g_sum[i] = 0.0; g_sumsq[i] = 0.0; }
}

__global__ void bn_finalize(const float* __restrict__ gamma, const float* __restrict__ beta) {
    int d = threadIdx.x;
    double cnt = (double)B_ * N_;
    double mu = g_sum[d] / cnt;
    double var = g_sumsq[d] / cnt - mu * mu;
    float w = gamma[d] * rsqrtf((float)var + EPS_);
    g_bnw[d] = w;
    g_bnb[d] = beta[d] - (float)mu * w;
}

__global__ void bn_final(float* __restrict__ out) {
    int i = blockIdx.x * 256 + threadIdx.x;  // N/4 per (d,b)
    int d = blockIdx.y, b = blockIdx.z;
    ll base = ((ll)b * C_ + d) * N_;
    uint2 raw = ((const uint2*)(g_Ph + base))[i];
    float2 f0 = __half22float2(*(__half2*)&raw.x);
    float2 f1 = __half22float2(*(__half2*)&raw.y);
    float w = g_bnw[d], bb = g_bnb[d];
    float4 o;
    o.x = fmaxf(f0.x * w + bb, 0.f);
    o.y = fmaxf(f0.y * w + bb, 0.f);
    o.z = fmaxf(f1.x * w + bb, 0.f);
    o.w = fmaxf(f1.y * w + bb, 0.f);
    ((float4*)(out + base))[i] = o;
}

// ---------------- fp16 TN GEMM: 3-stage cp.async pipeline ----------------
// EPI: 0 none, 1 ex2(h2)+rowsum (scale pre-folds log2e), 2 div-by-l
__device__ __forceinline__ void load_stage(uint32_t sb, const __half* A, const __half* Bg,
                                           int row0, int col0, int lda, int ldb,
                                           int k0, int tid) {
#pragma unroll
    for (int r = 0; r < 4; r++) {
        int lin = tid + r * 256;
        int row = lin >> 3, f4 = lin & 7;
        uint32_t so = (uint32_t)((row * 8 + (f4 ^ (row & 7))) * 16);
        cp16(sb + so, A + (ll)(row0 + row) * lda + k0 + f4 * 8);
        cp16(sb + 16384 + so, Bg + (ll)(col0 + row) * ldb + k0 + f4 * 8);
    }
}

template <int BIAS, int EPI, bool STATS>
__global__ __launch_bounds__(256, 2)
void gemm_tn(const __half* __restrict__ A, ll sA, ll sA2, int lda,
             const __half* __restrict__ Bg, ll sB, ll sB2, int ldb,
             __half* __restrict__ Cm, ll sC, ll sC2, int ldc, int Kd,
             const float* __restrict__ bias, int biasStr,
             float scale, double* stS, double* stQ,
             float* lrow, ll sL) {
    extern __shared__ char smc[];
    const uint32_t smu = (uint32_t)__cvta_generic_to_shared(smc);
    const int bz = blockIdx.z, side = bz >> 4, b = bz & 15;
    A += (ll)b * sA + (ll)side * sA2;
    Bg += (ll)b * sB + (ll)side * sB2;
    Cm += (ll)b * sC + (ll)side * sC2;
    if (BIAS) bias += side * biasStr;
    if (EPI) lrow += (ll)bz * sL;
    const int row0 = blockIdx.y * 128, col0 = blockIdx.x * 128;
    const int tid = threadIdx.x, lane = tid & 31, warp = tid >> 5;
    const int wm = warp >> 2, wn = warp & 3;
    const int rA = lane & 15, selA = lane >> 4;
    const int tb = lane & 15, rB = tb & 7, midB = tb >> 3;

    float acc[4][4][4];
#pragma unroll
    for (int i = 0; i < 4; i++)
#pragma unroll
        for (int j = 0; j < 4; j++)
#pragma unroll
            for (int q = 0; q < 4; q++) acc[i][j][q] = 0.f;

    const int nT = Kd / 64;
    load_stage(smu, A, Bg, row0, col0, lda, ldb, 0, tid); cp_commit();
    load_stage(smu + 32768, A, Bg, row0, col0, lda, ldb, 64, tid); cp_commit();

    for (int t = 0; t < nT; t++) {
        if (t + 2 < nT)
            load_stage(smu + (uint32_t)(((t + 2) % 3) * 32768), A, Bg,
                       row0, col0, lda, ldb, (t + 2) * 64, tid);
        cp_commit();           // empty group in tail keeps wait accounting exact
        cp_wait<2>();
        __syncthreads();

        uint32_t Au = smu + (uint32_t)((t % 3) * 32768);
        uint32_t Bu = Au + 16384;
#pragma unroll
        for (int kt = 0; kt < 4; kt++) {
            uint32_t af[4][4], bf4[4][2];
#pragma unroll
            for (int mt = 0; mt < 4; mt++) {
                int row = wm * 64 + mt * 16 + rA;
                int u = kt * 2 + selA;
                ldsm_x4(af[mt], Au + (uint32_t)((row * 8 + (u ^ (row & 7))) * 16));
            }
#pragma unroll
            for (int nt = 0; nt < 4; nt++) {
                int row = wn * 32 + nt * 8 + rB;
                int u = kt * 2 + midB;
                ldsm_x2(bf4[nt], Bu + (uint32_t)((row * 8 + (u ^ (row & 7))) * 16));
            }
#pragma unroll
            for (int mt = 0; mt < 4; mt++)
#pragma unroll
                for (int nt = 0; nt < 4; nt++)
                    mma_f16(acc[mt][nt], af[mt], bf4[nt]);
        }
        __syncthreads();
    }

    const int gr = lane >> 2, gc = (lane & 3) * 2;
#pragma unroll
    for (int mt = 0; mt < 4; mt++) {
        int r0 = row0 + wm * 64 + mt * 16 + gr;
        float inv0 = 1.f, inv1 = 1.f;
        if (EPI == 2) { inv0 = 1.f / lrow[r0]; inv1 = 1.f / lrow[r0 + 8]; }
        float s0 = 0.f, q0 = 0.f, s1 = 0.f, q1 = 0.f;
#pragma unroll
        for (int nt = 0; nt < 4; nt++) {
            int col = col0 + wn * 32 + nt * 8 + gc;
            float v0x = acc[mt][nt][0] * scale, v0y = acc[mt][nt][1] * scale;
            float v1x = acc[mt][nt][2] * scale, v1y = acc[mt][nt][3] * scale;
            if (BIAS == 1) {
                float bx = bias[col], by = bias[col + 1];
                v0x += bx; v0y += by; v1x += bx; v1y += by;
            } else if (BIAS == 2) {
                float b0v = bias[r0], b1v = bias[r0 + 8];
                v0x += b0v; v0y += b0v; v1x += b1v; v1y += b1v;
            }
            if (EPI == 1) {
                // scale already includes log2e: stored value = 2^(s*log2e/16) = e^(s/16)
                __half2 h0 = __floats2half2_rn(v0x, v0y);
                __half2 h1 = __floats2half2_rn(v1x, v1y);
                uint32_t e0 = ex2_h2(*(uint32_t*)&h0);
                uint32_t e1 = ex2_h2(*(uint32_t*)&h1);
                float2 f0 = __half22float2(*(__half2*)&e0);
                float2 f1 = __half22float2(*(__half2*)&e1);
                s0 += f0.x + f0.y; s1 += f1.x + f1.y;
                *(uint32_t*)(Cm + (ll)r0 * ldc + col) = e0;
                *(uint32_t*)(Cm + (ll)(r0 + 8) * ldc + col) = e1;
                continue;
            }
            if (EPI == 2) { v0x *= inv0; v0y *= inv0; v1x *= inv1; v1y *= inv1; }
            if (STATS) {
                s0 += v0x + v0y; q0 += v0x * v0x + v0y * v0y;
                s1 += v1x + v1y; q1 += v1x * v1x + v1y * v1y;
            }
            *(__half2*)(Cm + (ll)r0 * ldc + col) = __floats2half2_rn(v0x, v0y);
            *(__half2*)(Cm + (ll)(r0 + 8) * ldc + col) = __floats2half2_rn(v1x, v1y);
        }
        if (EPI == 1) {
            s0 += __shfl_xor_sync(0xffffffffu, s0, 1); s0 += __shfl_xor_sync(0xffffffffu, s0, 2);
            s1 += __shfl_xor_sync(0xffffffffu, s1, 1); s1 += __shfl_xor_sync(0xffffffffu, s1, 2);
            if ((lane & 3) == 0) {
                atomicAdd(&lrow[r0], s0);
                atomicAdd(&lrow[r0 + 8], s1);
            }
        }
        if (STATS) {
            s0 += __shfl_xor_sync(0xffffffffu, s0, 1); s0 += __shfl_xor_sync(0xffffffffu, s0, 2);
            q0 += __shfl_xor_sync(0xffffffffu, q0, 1); q0 += __shfl_xor_sync(0xffffffffu, q0, 2);
            s1 += __shfl_xor_sync(0xffffffffu, s1, 1); s1 += __shfl_xor_sync(0xffffffffu, s1, 2);
            q1 += __shfl_xor_sync(0xffffffffu, q1, 1); q1 += __shfl_xor_sync(0xffffffffu, q1, 2);
            if ((lane & 3) == 0) {
                atomicAdd(&stS[r0], (double)s0);
                atomicAdd(&stQ[r0], (double)q0);
                atomicAdd(&stS[r0 + 8], (double)s1);
                atomicAdd(&stQ[r0 + 8], (double)q1);
            }
        }
    }
}

template <int BIAS, int EPI, bool STATS>
static void launch_tn(const __half* A, ll sA, ll sA2, int lda,
                      const __half* Bg, ll sB, ll sB2, int ldb,
                      __half* Cm, ll sC, ll sC2, int ldc,
                      int Md, int Nd, int Kd,
                      const float* bias, int biasStr,
                      float scale, int batch,
                      double* stS, double* stQ, float* lrow, ll sL) {
    cudaFuncSetAttribute(gemm_tn<BIAS, EPI, STATS>,
                         cudaFuncAttributeMaxDynamicSharedMemorySize, 98304);
    dim3 grid(Nd / 128, Md / 128, batch);
    gemm_tn<BIAS, EPI, STATS><<<grid, 256, 98304>>>(
        A, sA, sA2, lda, Bg, sB, sB2, ldb, Cm, sC, sC2, ldc, Kd,
        bias, biasStr, scale, stS, stQ, lrow, sL);
}

// ---------------- driver ----------------
extern "C" void kernel_launch(void* const* d_in, const int* in_sizes, int n_in,
                              void* d_out, int out_size) {
    const float* x = (const float*)d_in[0];
    int pb = (n_in > 1 && in_sizes[1] == 1) ? 2 : 1;
    const float* P[20];
    for (int i = 0; i < 20; i++) P[i] = (const float*)d_in[pb + i];
    float* out = (float*)d_out;

    __half *cat, *ctxh, *Qh, *Kh, *Vth, *Sh, *Ph, *Wh, *W3;
    float *bp, *bc, *lptr;
    double *stS, *stQ;
    cudaGetSymbolAddress((void**)&cat, g_cat);
    cudaGetSymbolAddress((void**)&ctxh, g_ctxh);
    cudaGetSymbolAddress((void**)&Qh, g_Qh);
    cudaGetSymbolAddress((void**)&Kh, g_Kh);
    cudaGetSymbolAddress((void**)&Vth, g_Vth);
    cudaGetSymbolAddress((void**)&Sh, g_Sh);
    cudaGetSymbolAddress((void**)&Ph, g_Ph);
    cudaGetSymbolAddress((void**)&Wh, g_Wh);
    cudaGetSymbolAddress((void**)&W3, g_W3);
    cudaGetSymbolAddress((void**)&bp, g_bp);
    cudaGetSymbolAddress((void**)&bc, g_bc);
    cudaGetSymbolAddress((void**)&lptr, g_l);
    cudaGetSymbolAddress((void**)&stS, g_sum);
    cudaGetSymbolAddress((void**)&stQ, g_sumsq);

    const int CC = C_ * C_;
    const float LOG2E = 1.4426950408889634f;

    transpose_kernel<<<dim3(N_ / 32, C_ / 32, B_), dim3(32, 8)>>>(x);
    mean_kernel<<<dim3(C_, B_), 256>>>(x);
    score_kernel<<<dim3(N_ / 256, B_), 256>>>(x);
    sort_kernel<<<B_, 1024>>>();
    gather_kernel<<<dim3(M_ / 8, B_, 2), 256>>>();
    pack_w<<<1536, 256>>>(P[0], P[8], P[2], P[10], P[4], P[12]);
    pack_b<<<6, 256>>>(P[1], P[9], P[3], P[11], P[5], P[13]);
    combine_w<<<256, 256>>>(P[16], P[6], P[14], P[17], P[7], P[15]);
    zero_kernel<<<512, 256>>>();

    // Q (both sides)
    launch_tn<1, 0, false>(cat + 512, (ll)N_ * 768, 0, 768,
                           Wh, 0, 0, C_,
                           Qh, (ll)N_ * 512, 0, 512,
                           N_, 512, C_, bp, 0, 1.f, B_, nullptr, nullptr, nullptr, 0);
    // K
    launch_tn<1, 0, false>(ctxh, (ll)M_ * C_, (ll)B_ * M_ * C_, C_,
                           Wh + 2 * CC, 0, CC, C_,
                           Kh, (ll)M_ * C_, (ll)B_ * M_ * C_, C_,
                           M_, C_, C_, bp + 512, 256, 1.f, 2 * B_, nullptr, nullptr, nullptr, 0);
    // V^T
    launch_tn<2, 0, false>(Wh + 4 * CC, 0, CC, C_,
                           ctxh, (ll)M_ * C_, (ll)B_ * M_ * C_, C_,
                           Vth, (ll)C_ * M_, (ll)B_ * C_ * M_, M_,
                           C_, M_, C_, bp + 1024, 256, 1.f, 2 * B_, nullptr, nullptr, nullptr, 0);
    // S~ = 2^(Q·K^T * log2e/16), row sums
    launch_tn<0, 1, false>(Qh, (ll)N_ * 512, (ll)C_, 512,
                           Kh, (ll)M_ * C_, (ll)B_ * M_ * C_, C_,
                           Sh, (ll)N_ * M_, (ll)B_ * N_ * M_, M_,
                           N_, M_, C_, nullptr, 0, LOG2E / 16.f, 2 * B_,
                           nullptr, nullptr, lptr, N_);
    // Y = (S~·V)/l -> cat slots
    launch_tn<0, 2, false>(Sh, (ll)N_ * M_, (ll)B_ * N_ * M_, M_,
                           Vth, (ll)C_ * M_, (ll)B_ * C_ * M_, M_,
                           cat, (ll)N_ * 768, 256, 768,
                           N_, C_, M_, nullptr, 0, 1.f, 2 * B_,
                           nullptr, nullptr, lptr, N_);
    // fuse + BN stats
    launch_tn<2, 0, true>(W3, 0, 0, 768,
                          cat, (ll)N_ * 768, 0, 768,
                          Ph, (ll)C_ * N_, 0, N_,
                          C_, N_, 768, bc, 0, 1.f, B_, stS, stQ, nullptr, 0);

    bn_finalize<<<1, 256>>>(P[18], P[19]);
    bn_final<<<dim3(N_ / 1024, C_, B_), 256>>>(out);
}

// round 10
// speedup vs baseline: 1.6369x; 1.0413x over previous
#include <cuda_runtime.h>
#include <cuda_fp16.h>
#include <cstdint>

#define B_ 16
#define C_ 256
#define N_ 4096
#define M_ 1024
#define EPS_ 1e-5f
typedef long long ll;

// ---------------- scratch ----------------
__device__ float g_xm[B_ * C_];
__device__ float g_score[B_ * N_];
__device__ int   g_idx[2 * B_ * M_];
__device__ double g_sum[C_];
__device__ double g_sumsq[C_];
__device__ float g_bnw[C_];
__device__ float g_bnb[C_];
__device__ float g_bp[3 * 512];          // packed biases: bq2|bk2|bv2
__device__ float g_bc[C_];               // bconst for final gemm
__device__ float g_l[2 * B_ * N_];       // softmax row sums

__device__ __half g_cat[(ll)B_ * N_ * 768];   // [b][n][ Y_s(256) | Y_g(256) | x(256) ]
__device__ __half g_ctxh[2LL * B_ * M_ * C_]; // [side][b][m][c]
__device__ __half g_Qh[(ll)B_ * N_ * 512];    // [b][n][512]
__device__ __half g_Kh[2LL * B_ * M_ * C_];
__device__ __half g_Vth[2LL * B_ * C_ * M_];  // [side][b][d][m]
__device__ __half g_Sh[2LL * B_ * N_ * M_];   // unnormalized exp scores
__device__ __half g_Ph[(ll)B_ * C_ * N_];     // pre-BN output
__device__ __half g_Wh[6 * C_ * C_];          // Wq_s,Wq_g,Wk_s,Wk_g,Wv_s,Wv_g
__device__ __half g_W3[C_ * 768];             // [Wc_s | Wc_g | Wx]

// ---------------- PTX ----------------
__device__ __forceinline__ void cp16(uint32_t dst, const void* src) {
    asm volatile("cp.async.cg.shared.global [%0], [%1], 16;" :: "r"(dst), "l"(src));
}
__device__ __forceinline__ void cp_commit() { asm volatile("cp.async.commit_group;"); }
template <int Nw> __device__ __forceinline__ void cp_wait() {
    asm volatile("cp.async.wait_group %0;" :: "n"(Nw));
}
__device__ __forceinline__ void ldsm_x4(uint32_t* r, uint32_t a) {
    asm volatile("ldmatrix.sync.aligned.m8n8.x4.shared.b16 {%0,%1,%2,%3}, [%4];"
        : "=r"(r[0]), "=r"(r[1]), "=r"(r[2]), "=r"(r[3]) : "r"(a));
}
__device__ __forceinline__ void ldsm_x2(uint32_t* r, uint32_t a) {
    asm volatile("ldmatrix.sync.aligned.m8n8.x2.shared.b16 {%0,%1}, [%2];"
        : "=r"(r[0]), "=r"(r[1]) : "r"(a));
}
__device__ __forceinline__ void mma_f16(float* c, const uint32_t* a, const uint32_t* b) {
    asm volatile("mma.sync.aligned.m16n8k16.row.col.f32.f16.f16.f32 "
        "{%0,%1,%2,%3}, {%4,%5,%6,%7}, {%8,%9}, {%0,%1,%2,%3};"
        : "+f"(c[0]), "+f"(c[1]), "+f"(c[2]), "+f"(c[3])
        : "r"(a[0]), "r"(a[1]), "r"(a[2]), "r"(a[3]), "r"(b[0]), "r"(b[1]));
}
__device__ __forceinline__ uint32_t ex2_h2(uint32_t u) {
    asm("ex2.approx.f16x2 %0, %0;" : "+r"(u));
    return u;
}

// ---------------- small kernels ----------------
__global__ void zero_kernel() {
    int i = blockIdx.x * 256 + threadIdx.x;  // 131072 threads
    if (i < 2 * B_ * N_) g_l[i] = 0.f;
    if (i < B_ * C_) g_xm[i] = 0.f;
    if (i < C_) { g_sum[i] = 0.0; g_sumsq[i] = 0.0; }
}

// transpose fp32 [b][c][n] -> fp16 cat x-slot [b][n][c]; fused mean accumulation
__global__ void transpose_kernel(const float* __restrict__ x) {
    __shared__ float t[32][33];
    __shared__ float ps[32][9];
    int b = blockIdx.z, n0 = blockIdx.x * 32, c0 = blockIdx.y * 32;
    int tx = threadIdx.x, ty = threadIdx.y;  // (32, 8)
    const float* xp = x + (ll)b * C_ * N_;
    __half* xhp = g_cat + (ll)b * N_ * 768 + 512;
#pragma unroll
    for (int i = 0; i < 32; i += 8)
        t[ty + i][tx] = xp[(ll)(c0 + ty + i) * N_ + n0 + tx];
    __syncthreads();
#pragma unroll
    for (int i = 0; i < 32; i += 8)
        xhp[(ll)(n0 + ty + i) * 768 + c0 + tx] = __float2half_rn(t[tx][ty + i]);
    // per-channel partial sums: channel = c0+tx, sum over this tile's 32 n
    float s = 0.f;
#pragma unroll
    for (int q = 0; q < 4; q++) s += t[tx][ty * 4 + q];
    ps[tx][ty] = s;
    __syncthreads();
    if (ty == 0) {
        float tot = 0.f;
#pragma unroll
        for (int q = 0; q < 8; q++) tot += ps[tx][q];
        atomicAdd(&g_xm[b * C_ + c0 + tx], tot * (1.0f / N_));
    }
}

__global__ void score_kernel(const float* __restrict__ x) {
    int n = blockIdx.x * 256 + threadIdx.x;
    int b = blockIdx.y;
    const float* px = x + (ll)b * C_ * N_;
    const float* pm = g_xm + b * C_;
    float s = 0.f;
#pragma unroll 8
    for (int c = 0; c < C_; c++) {
        float d = px[(ll)c * N_ + n] - pm[c];
        s += d * d;
    }
    g_score[b * N_ + n] = s;  // >= 0, so float bits are order-isomorphic as uint
}

// radix-select top-M and bottom-M per batch (set semantics; order-free)
__global__ void select_kernel() {
    __shared__ uint32_t sv[N_];
    __shared__ int hist[256];
    __shared__ int s_digit, s_k, s_cnt, s_base;
    int b = blockIdx.x, t = threadIdx.x;  // 1024 threads
    for (int i = t; i < N_; i += 1024) sv[i] = __float_as_uint(g_score[b * N_ + i]);
    __syncthreads();

#pragma unroll
    for (int dir = 0; dir < 2; dir++) {  // 0: largest M (sharp), 1: smallest M (gentle)
        uint32_t prefix = 0, pmask = 0;
        int k = M_;
        for (int pass = 0; pass < 4; pass++) {
            int shift = 24 - 8 * pass;
            if (t < 256) hist[t] = 0;
            __syncthreads();
            for (int i = t; i < N_; i += 1024) {
                uint32_t v = sv[i];
                if ((v & pmask) == prefix) atomicAdd(&hist[(v >> shift) & 255], 1);
            }
            __syncthreads();
            if (t == 0) {
                int cum = 0, d;
                if (dir == 0) {
                    for (d = 255; d > 0; d--) {
                        int c = hist[d];
                        if (cum + c >= k) break;
                        cum += c;
                    }
                } else {
                    for (d = 0; d < 255; d++) {
                        int c = hist[d];
                        if (cum + c >= k) break;
                        cum += c;
                    }
                }
                s_digit = d; s_k = k - cum;
            }
            __syncthreads();
            prefix |= ((uint32_t)s_digit) << shift;
            pmask |= 0xFFu << shift;
            k = s_k;
            __syncthreads();
        }
        uint32_t T = prefix;
        int keq = k;  // how many elements equal to T belong in the set
        if (t == 0) s_cnt = 0;
        __syncthreads();
        int* dst = g_idx + dir * B_ * M_ + b * M_;
        for (int i = t; i < N_; i += 1024) {
            uint32_t v = sv[i];
            bool strict = (dir == 0) ? (v > T) : (v < T);
            if (strict) dst[atomicAdd(&s_cnt, 1)] = i;
        }
        __syncthreads();
        if (t == 0) { s_base = s_cnt; s_cnt = 0; }
        __syncthreads();
        for (int i = t; i < N_; i += 1024) {
            if (sv[i] == T) {
                int e = atomicAdd(&s_cnt, 1);
                if (e < keq) dst[s_base + e] = i;
            }
        }
        __syncthreads();
    }
}

__global__ void gather_kernel() {
    int side = blockIdx.z, b = blockIdx.y;
    int m = blockIdx.x * 8 + (threadIdx.x >> 5);
    int c8 = threadIdx.x & 31;
    int j = g_idx[side * B_ * M_ + b * M_ + m];
    uint4 v = ((const uint4*)(g_cat + ((ll)b * N_ + j) * 768 + 512))[c8];
    ((uint4*)(g_ctxh + (((ll)side * B_ + b) * M_ + m) * C_))[c8] = v;
}

__global__ void pack_w(const float* a0, const float* a1, const float* a2,
                       const float* a3, const float* a4, const float* a5) {
    int i = blockIdx.x * 256 + threadIdx.x;
    const float* p[6] = {a0, a1, a2, a3, a4, a5};
    g_Wh[i] = __float2half_rn(p[i >> 16][i & 65535]);
}

__global__ void pack_b(const float* b0, const float* b1, const float* b2,
                       const float* b3, const float* b4, const float* b5) {
    int i = threadIdx.x + blockIdx.x * 256;
    const float* p[6] = {b0, b1, b2, b3, b4, b5};
    int grp = i >> 9, k = i & 511;
    g_bp[i] = p[(grp << 1) | (k >> 8)][k & 255];
}

__global__ void combine_w(const float* __restrict__ Wf,
                          const float* __restrict__ Wo_s, const float* __restrict__ Wo_g,
                          const float* __restrict__ bf,
                          const float* __restrict__ bo_s, const float* __restrict__ bo_g) {
    int d = blockIdx.x, t = threadIdx.x;
    __shared__ float wf[512];
    wf[t] = Wf[d * 512 + t];
    wf[t + 256] = Wf[d * 512 + 256 + t];
    __syncthreads();
    float a0 = 0.f, a1 = 0.f;
#pragma unroll 4
    for (int e = 0; e < 256; e++) {
        a0 += wf[e] * Wo_s[e * 256 + t];
        a1 += wf[256 + e] * Wo_g[e * 256 + t];
    }
    g_W3[d * 768 + t] = __float2half_rn(a0);
    g_W3[d * 768 + 256 + t] = __float2half_rn(a1);
    g_W3[d * 768 + 512 + t] = __float2half_rn(wf[t] + wf[256 + t]);
    if (t == 0) {
        float bc = bf[d];
        for (int e = 0; e < 256; e++) bc += wf[e] * bo_s[e] + wf[256 + e] * bo_g[e];
        g_bc[d] = bc;
    }
}

__global__ void bn_finalize(const float* __restrict__ gamma, const float* __restrict__ beta) {
    int d = threadIdx.x;
    double cnt = (double)B_ * N_;
    double mu = g_sum[d] / cnt;
    double var = g_sumsq[d] / cnt - mu * mu;
    float w = gamma[d] * rsqrtf((float)var + EPS_);
    g_bnw[d] = w;
    g_bnb[d] = beta[d] - (float)mu * w;
}

__global__ void bn_final(float* __restrict__ out) {
    int i = blockIdx.x * 256 + threadIdx.x;  // N/4 per (d,b)
    int d = blockIdx.y, b = blockIdx.z;
    ll base = ((ll)b * C_ + d) * N_;
    uint2 raw = ((const uint2*)(g_Ph + base))[i];
    float2 f0 = __half22float2(*(__half2*)&raw.x);
    float2 f1 = __half22float2(*(__half2*)&raw.y);
    float w = g_bnw[d], bb = g_bnb[d];
    float4 o;
    o.x = fmaxf(f0.x * w + bb, 0.f);
    o.y = fmaxf(f0.y * w + bb, 0.f);
    o.z = fmaxf(f1.x * w + bb, 0.f);
    o.w = fmaxf(f1.y * w + bb, 0.f);
    ((float4*)(out + base))[i] = o;
}

// ---------------- fp16 TN GEMM: 3-stage cp.async pipeline ----------------
// EPI: 0 none, 1 ex2(h2)+rowsum (scale pre-folds log2e), 2 div-by-l
__device__ __forceinline__ void load_stage(uint32_t sb, const __half* A, const __half* Bg,
                                           int row0, int col0, int lda, int ldb,
                                           int k0, int tid) {
#pragma unroll
    for (int r = 0; r < 4; r++) {
        int lin = tid + r * 256;
        int row = lin >> 3, f4 = lin & 7;
        uint32_t so = (uint32_t)((row * 8 + (f4 ^ (row & 7))) * 16);
        cp16(sb + so, A + (ll)(row0 + row) * lda + k0 + f4 * 8);
        cp16(sb + 16384 + so, Bg + (ll)(col0 + row) * ldb + k0 + f4 * 8);
    }
}

template <int BIAS, int EPI, bool STATS>
__global__ __launch_bounds__(256, 2)
void gemm_tn(const __half* __restrict__ A, ll sA, ll sA2, int lda,
             const __half* __restrict__ Bg, ll sB, ll sB2, int ldb,
             __half* __restrict__ Cm, ll sC, ll sC2, int ldc, int Kd,
             const float* __restrict__ bias, int biasStr,
             float scale, double* stS, double* stQ,
             float* lrow, ll sL) {
    extern __shared__ char smc[];
    const uint32_t smu = (uint32_t)__cvta_generic_to_shared(smc);
    const int bz = blockIdx.z, side = bz >> 4, b = bz & 15;
    A += (ll)b * sA + (ll)side * sA2;
    Bg += (ll)b * sB + (ll)side * sB2;
    Cm += (ll)b * sC + (ll)side * sC2;
    if (BIAS) bias += side * biasStr;
    if (EPI) lrow += (ll)bz * sL;
    const int row0 = blockIdx.y * 128, col0 = blockIdx.x * 128;
    const int tid = threadIdx.x, lane = tid & 31, warp = tid >> 5;
    const int wm = warp >> 2, wn = warp & 3;
    const int rA = lane & 15, selA = lane >> 4;
    const int tb = lane & 15, rB = tb & 7, midB = tb >> 3;

    float acc[4][4][4];
#pragma unroll
    for (int i = 0; i < 4; i++)
#pragma unroll
        for (int j = 0; j < 4; j++)
#pragma unroll
            for (int q = 0; q < 4; q++) acc[i][j][q] = 0.f;

    const int nT = Kd / 64;
    load_stage(smu, A, Bg, row0, col0, lda, ldb, 0, tid); cp_commit();
    load_stage(smu + 32768, A, Bg, row0, col0, lda, ldb, 64, tid); cp_commit();

    for (int t = 0; t < nT; t++) {
        if (t + 2 < nT)
            load_stage(smu + (uint32_t)(((t + 2) % 3) * 32768), A, Bg,
                       row0, col0, lda, ldb, (t + 2) * 64, tid);
        cp_commit();
        cp_wait<2>();
        __syncthreads();

        uint32_t Au = smu + (uint32_t)((t % 3) * 32768);
        uint32_t Bu = Au + 16384;
#pragma unroll
        for (int kt = 0; kt < 4; kt++) {
            uint32_t af[4][4], bf4[4][2];
#pragma unroll
            for (int mt = 0; mt < 4; mt++) {
                int row = wm * 64 + mt * 16 + rA;
                int u = kt * 2 + selA;
                ldsm_x4(af[mt], Au + (uint32_t)((row * 8 + (u ^ (row & 7))) * 16));
            }
#pragma unroll
            for (int nt = 0; nt < 4; nt++) {
                int row = wn * 32 + nt * 8 + rB;
                int u = kt * 2 + midB;
                ldsm_x2(bf4[nt], Bu + (uint32_t)((row * 8 + (u ^ (row & 7))) * 16));
            }
#pragma unroll
            for (int mt = 0; mt < 4; mt++)
#pragma unroll
                for (int nt = 0; nt < 4; nt++)
                    mma_f16(acc[mt][nt], af[mt], bf4[nt]);
        }
        __syncthreads();
    }

    const int gr = lane >> 2, gc = (lane & 3) * 2;
#pragma unroll
    for (int mt = 0; mt < 4; mt++) {
        int r0 = row0 + wm * 64 + mt * 16 + gr;
        float inv0 = 1.f, inv1 = 1.f;
        if (EPI == 2) { inv0 = 1.f / lrow[r0]; inv1 = 1.f / lrow[r0 + 8]; }
        float s0 = 0.f, q0 = 0.f, s1 = 0.f, q1 = 0.f;
#pragma unroll
        for (int nt = 0; nt < 4; nt++) {
            int col = col0 + wn * 32 + nt * 8 + gc;
            float v0x = acc[mt][nt][0] * scale, v0y = acc[mt][nt][1] * scale;
            float v1x = acc[mt][nt][2] * scale, v1y = acc[mt][nt][3] * scale;
            if (BIAS == 1) {
                float bx = bias[col], by = bias[col + 1];
                v0x += bx; v0y += by; v1x += bx; v1y += by;
            } else if (BIAS == 2) {
                float b0v = bias[r0], b1v = bias[r0 + 8];
                v0x += b0v; v0y += b0v; v1x += b1v; v1y += b1v;
            }
            if (EPI == 1) {
                __half2 h0 = __floats2half2_rn(v0x, v0y);
                __half2 h1 = __floats2half2_rn(v1x, v1y);
                uint32_t e0 = ex2_h2(*(uint32_t*)&h0);
                uint32_t e1 = ex2_h2(*(uint32_t*)&h1);
                float2 f0 = __half22float2(*(__half2*)&e0);
                float2 f1 = __half22float2(*(__half2*)&e1);
                s0 += f0.x + f0.y; s1 += f1.x + f1.y;
                *(uint32_t*)(Cm + (ll)r0 * ldc + col) = e0;
                *(uint32_t*)(Cm + (ll)(r0 + 8) * ldc + col) = e1;
                continue;
            }
            if (EPI == 2) { v0x *= inv0; v0y *= inv0; v1x *= inv1; v1y *= inv1; }
            if (STATS) {
                s0 += v0x + v0y; q0 += v0x * v0x + v0y * v0y;
                s1 += v1x + v1y; q1 += v1x * v1x + v1y * v1y;
            }
            *(__half2*)(Cm + (ll)r0 * ldc + col) = __floats2half2_rn(v0x, v0y);
            *(__half2*)(Cm + (ll)(r0 + 8) * ldc + col) = __floats2half2_rn(v1x, v1y);
        }
        if (EPI == 1) {
            s0 += __shfl_xor_sync(0xffffffffu, s0, 1); s0 += __shfl_xor_sync(0xffffffffu, s0, 2);
            s1 += __shfl_xor_sync(0xffffffffu, s1, 1); s1 += __shfl_xor_sync(0xffffffffu, s1, 2);
            if ((lane & 3) == 0) {
                atomicAdd(&lrow[r0], s0);
                atomicAdd(&lrow[r0 + 8], s1);
            }
        }
        if (STATS) {
            s0 += __shfl_xor_sync(0xffffffffu, s0, 1); s0 += __shfl_xor_sync(0xffffffffu, s0, 2);
            q0 += __shfl_xor_sync(0xffffffffu, q0, 1); q0 += __shfl_xor_sync(0xffffffffu, q0, 2);
            s1 += __shfl_xor_sync(0xffffffffu, s1, 1); s1 += __shfl_xor_sync(0xffffffffu, s1, 2);
            q1 += __shfl_xor_sync(0xffffffffu, q1, 1); q1 += __shfl_xor_sync(0xffffffffu, q1, 2);
            if ((lane & 3) == 0) {
                atomicAdd(&stS[r0], (double)s0);
                atomicAdd(&stQ[r0], (double)q0);
                atomicAdd(&stS[r0 + 8], (double)s1);
                atomicAdd(&stQ[r0 + 8], (double)q1);
            }
        }
    }
}

template <int BIAS, int EPI, bool STATS>
static void launch_tn(const __half* A, ll sA, ll sA2, int lda,
                      const __half* Bg, ll sB, ll sB2, int ldb,
                      __half* Cm, ll sC, ll sC2, int ldc,
                      int Md, int Nd, int Kd,
                      const float* bias, int biasStr,
                      float scale, int batch,
                      double* stS, double* stQ, float* lrow, ll sL) {
    cudaFuncSetAttribute(gemm_tn<BIAS, EPI, STATS>,
                         cudaFuncAttributeMaxDynamicSharedMemorySize, 98304);
    dim3 grid(Nd / 128, Md / 128, batch);
    gemm_tn<BIAS, EPI, STATS><<<grid, 256, 98304>>>(
        A, sA, sA2, lda, Bg, sB, sB2, ldb, Cm, sC, sC2, ldc, Kd,
        bias, biasStr, scale, stS, stQ, lrow, sL);
}

// ---------------- driver ----------------
extern "C" void kernel_launch(void* const* d_in, const int* in_sizes, int n_in,
                              void* d_out, int out_size) {
    const float* x = (const float*)d_in[0];
    int pb = (n_in > 1 && in_sizes[1] == 1) ? 2 : 1;
    const float* P[20];
    for (int i = 0; i < 20; i++) P[i] = (const float*)d_in[pb + i];
    float* out = (float*)d_out;

    __half *cat, *ctxh, *Qh, *Kh, *Vth, *Sh, *Ph, *Wh, *W3;
    float *bp, *bc, *lptr;
    double *stS, *stQ;
    cudaGetSymbolAddress((void**)&cat, g_cat);
    cudaGetSymbolAddress((void**)&ctxh, g_ctxh);
    cudaGetSymbolAddress((void**)&Qh, g_Qh);
    cudaGetSymbolAddress((void**)&Kh, g_Kh);
    cudaGetSymbolAddress((void**)&Vth, g_Vth);
    cudaGetSymbolAddress((void**)&Sh, g_Sh);
    cudaGetSymbolAddress((void**)&Ph, g_Ph);
    cudaGetSymbolAddress((void**)&Wh, g_Wh);
    cudaGetSymbolAddress((void**)&W3, g_W3);
    cudaGetSymbolAddress((void**)&bp, g_bp);
    cudaGetSymbolAddress((void**)&bc, g_bc);
    cudaGetSymbolAddress((void**)&lptr, g_l);
    cudaGetSymbolAddress((void**)&stS, g_sum);
    cudaGetSymbolAddress((void**)&stQ, g_sumsq);

    const int CC = C_ * C_;
    const float LOG2E = 1.4426950408889634f;

    zero_kernel<<<512, 256>>>();
    transpose_kernel<<<dim3(N_ / 32, C_ / 32, B_), dim3(32, 8)>>>(x);
    score_kernel<<<dim3(N_ / 256, B_), 256>>>(x);
    select_kernel<<<B_, 1024>>>();
    gather_kernel<<<dim3(M_ / 8, B_, 2), 256>>>();
    pack_w<<<1536, 256>>>(P[0], P[8], P[2], P[10], P[4], P[12]);
    pack_b<<<6, 256>>>(P[1], P[9], P[3], P[11], P[5], P[13]);
    combine_w<<<256, 256>>>(P[16], P[6], P[14], P[17], P[7], P[15]);

    // Q (both sides)
    launch_tn<1, 0, false>(cat + 512, (ll)N_ * 768, 0, 768,
                           Wh, 0, 0, C_,
                           Qh, (ll)N_ * 512, 0, 512,
                           N_, 512, C_, bp, 0, 1.f, B_, nullptr, nullptr, nullptr, 0);
    // K
    launch_tn<1, 0, false>(ctxh, (ll)M_ * C_, (ll)B_ * M_ * C_, C_,
                           Wh + 2 * CC, 0, CC, C_,
                           Kh, (ll)M_ * C_, (ll)B_ * M_ * C_, C_,
                           M_, C_, C_, bp + 512, 256, 1.f, 2 * B_, nullptr, nullptr, nullptr, 0);
    // V^T
    launch_tn<2, 0, false>(Wh + 4 * CC, 0, CC, C_,
                           ctxh, (ll)M_ * C_, (ll)B_ * M_ * C_, C_,
                           Vth, (ll)C_ * M_, (ll)B_ * C_ * M_, M_,
                           C_, M_, C_, bp + 1024, 256, 1.f, 2 * B_, nullptr, nullptr, nullptr, 0);
    // S~ = 2^(Q·K^T * log2e/16), row sums
    launch_tn<0, 1, false>(Qh, (ll)N_ * 512, (ll)C_, 512,
                           Kh, (ll)M_ * C_, (ll)B_ * M_ * C_, C_,
                           Sh, (ll)N_ * M_, (ll)B_ * N_ * M_, M_,
                           N_, M_, C_, nullptr, 0, LOG2E / 16.f, 2 * B_,
                           nullptr, nullptr, lptr, N_);
    // Y = (S~·V)/l -> cat slots
    launch_tn<0, 2, false>(Sh, (ll)N_ * M_, (ll)B_ * N_ * M_, M_,
                           Vth, (ll)C_ * M_, (ll)B_ * C_ * M_, M_,
                           cat, (ll)N_ * 768, 256, 768,
                           N_, C_, M_, nullptr, 0, 1.f, 2 * B_,
                           nullptr, nullptr, lptr, N_);
    // fuse + BN stats
    launch_tn<2, 0, true>(W3, 0, 0, 768,
                          cat, (ll)N_ * 768, 0, 768,
                          Ph, (ll)C_ * N_, 0, N_,
                          C_, N_, 768, bc, 0, 1.f, B_, stS, stQ, nullptr, 0);

    bn_finalize<<<1, 256>>>(P[18], P[19]);
    bn_final<<<dim3(N_ / 1024, C_, B_), 256>>>(out);
}

// round 11
// speedup vs baseline: 1.6832x; 1.0283x over previous
#include <cuda_runtime.h>
#include <cuda_fp16.h>
#include <cstdint>

#define B_ 16
#define C_ 256
#define N_ 4096
#define M_ 1024
#define EPS_ 1e-5f
typedef long long ll;

// ---------------- scratch ----------------
__device__ float g_xm[B_ * C_];
__device__ float g_score[B_ * N_];
__device__ int   g_idx[2 * B_ * M_];
__device__ double g_sum[C_];
__device__ double g_sumsq[C_];
__device__ float g_bnw[C_];
__device__ float g_bnb[C_];
__device__ float g_bp[3 * 512];          // packed biases: bq2|bk2|bv2
__device__ float g_bc[C_];               // bconst for final gemm
__device__ float g_l[2 * B_ * N_];       // softmax row sums

__device__ __half g_cat[(ll)B_ * N_ * 768];   // [b][n][ Y_s(256) | Y_g(256) | x(256) ]
__device__ __half g_ctxh[2LL * B_ * M_ * C_]; // [side][b][m][c]
__device__ __half g_Qh[(ll)B_ * N_ * 512];    // [b][n][512]
__device__ __half g_Kh[2LL * B_ * M_ * C_];
__device__ __half g_Vth[2LL * B_ * C_ * M_];  // [side][b][d][m]
__device__ __half g_Sh[2LL * B_ * N_ * M_];   // unnormalized exp scores
__device__ __half g_Ph[(ll)B_ * C_ * N_];     // pre-BN output
__device__ __half g_Wh[6 * C_ * C_];          // Wq_s,Wq_g,Wk_s,Wk_g,Wv_s,Wv_g
__device__ __half g_W3[C_ * 768];             // [Wc_s | Wc_g | Wx]

// ---------------- PTX ----------------
__device__ __forceinline__ void cp16(uint32_t dst, const void* src) {
    asm volatile("cp.async.cg.shared.global [%0], [%1], 16;" :: "r"(dst), "l"(src));
}
__device__ __forceinline__ void cp_commit() { asm volatile("cp.async.commit_group;"); }
template <int Nw> __device__ __forceinline__ void cp_wait() {
    asm volatile("cp.async.wait_group %0;" :: "n"(Nw));
}
__device__ __forceinline__ void ldsm_x4(uint32_t* r, uint32_t a) {
    asm volatile("ldmatrix.sync.aligned.m8n8.x4.shared.b16 {%0,%1,%2,%3}, [%4];"
        : "=r"(r[0]), "=r"(r[1]), "=r"(r[2]), "=r"(r[3]) : "r"(a));
}
__device__ __forceinline__ void ldsm_x2(uint32_t* r, uint32_t a) {
    asm volatile("ldmatrix.sync.aligned.m8n8.x2.shared.b16 {%0,%1}, [%2];"
        : "=r"(r[0]), "=r"(r[1]) : "r"(a));
}
__device__ __forceinline__ void mma_f16(float* c, const uint32_t* a, const uint32_t* b) {
    asm volatile("mma.sync.aligned.m16n8k16.row.col.f32.f16.f16.f32 "
        "{%0,%1,%2,%3}, {%4,%5,%6,%7}, {%8,%9}, {%0,%1,%2,%3};"
        : "+f"(c[0]), "+f"(c[1]), "+f"(c[2]), "+f"(c[3])
        : "r"(a[0]), "r"(a[1]), "r"(a[2]), "r"(a[3]), "r"(b[0]), "r"(b[1]));
}
__device__ __forceinline__ uint32_t ex2_h2(uint32_t u) {
    asm("ex2.approx.f16x2 %0, %0;" : "+r"(u));
    return u;
}

// ---------------- small kernels ----------------
// transpose fp32 [b][c][n] -> fp16 cat x-slot [b][n][c]; fused mean accumulation
__global__ void transpose_kernel(const float* __restrict__ x) {
    __shared__ float t[32][33];
    __shared__ float ps[32][9];
    int b = blockIdx.z, n0 = blockIdx.x * 32, c0 = blockIdx.y * 32;
    int tx = threadIdx.x, ty = threadIdx.y;  // (32, 8)
    const float* xp = x + (ll)b * C_ * N_;
    __half* xhp = g_cat + (ll)b * N_ * 768 + 512;
#pragma unroll
    for (int i = 0; i < 32; i += 8)
        t[ty + i][tx] = xp[(ll)(c0 + ty + i) * N_ + n0 + tx];
    __syncthreads();
#pragma unroll
    for (int i = 0; i < 32; i += 8)
        xhp[(ll)(n0 + ty + i) * 768 + c0 + tx] = __float2half_rn(t[tx][ty + i]);
    float s = 0.f;
#pragma unroll
    for (int q = 0; q < 4; q++) s += t[tx][ty * 4 + q];
    ps[tx][ty] = s;
    __syncthreads();
    if (ty == 0) {
        float tot = 0.f;
#pragma unroll
        for (int q = 0; q < 8; q++) tot += ps[tx][q];
        atomicAdd(&g_xm[b * C_ + c0 + tx], tot * (1.0f / N_));
    }
}

__global__ void score_kernel(const float* __restrict__ x) {
    int n = blockIdx.x * 256 + threadIdx.x;
    int b = blockIdx.y;
    const float* px = x + (ll)b * C_ * N_;
    const float* pm = g_xm + b * C_;
    float s = 0.f;
#pragma unroll 8
    for (int c = 0; c < C_; c++) {
        float d = px[(ll)c * N_ + n] - pm[c];
        s += d * d;
    }
    g_score[b * N_ + n] = s;  // >= 0: float bits order-isomorphic as uint
}

// radix-select top-M and bottom-M per batch; parallel prefix-scan digit find
__global__ void select_kernel() {
    __shared__ uint32_t sv[N_];
    __shared__ int hist[256];
    __shared__ int pre[257];
    __shared__ int s_digit, s_k, s_cnt, s_base;
    int b = blockIdx.x, t = threadIdx.x;  // 1024 threads
    for (int i = t; i < N_; i += 1024) sv[i] = __float_as_uint(g_score[b * N_ + i]);
    __syncthreads();

#pragma unroll
    for (int dir = 0; dir < 2; dir++) {  // 0: largest M (sharp), 1: smallest M (gentle)
        uint32_t prefix = 0, pmask = 0;
        int k = M_;
        for (int pass = 0; pass < 4; pass++) {
            int shift = 24 - 8 * pass;
            if (t < 256) hist[t] = 0;
            __syncthreads();
            for (int i = t; i < N_; i += 1024) {
                uint32_t v = sv[i];
                if ((v & pmask) == prefix) atomicAdd(&hist[(v >> shift) & 255], 1);
            }
            __syncthreads();
            // inclusive prefix scan of hist into pre[1..256], pre[0]=0
            if (t < 256) pre[t + 1] = hist[t];
            if (t == 0) pre[0] = 0;
            __syncthreads();
#pragma unroll
            for (int off = 1; off < 256; off <<= 1) {
                int v = 0;
                if (t < 256 && (int)t >= off) v = pre[t + 1 - off];
                __syncthreads();
                if (t < 256) pre[t + 1] += v;
                __syncthreads();
            }
            if (t < 256) {
                if (dir == 0) {
                    int above = pre[256] - pre[t + 1];   // count with digit > t
                    int atLeast = pre[256] - pre[t];     // count with digit >= t
                    if (atLeast >= k && above < k) { s_digit = t; s_k = k - above; }
                } else {
                    if (pre[t + 1] >= k && pre[t] < k) { s_digit = t; s_k = k - pre[t]; }
                }
            }
            __syncthreads();
            prefix |= ((uint32_t)s_digit) << shift;
            pmask |= 0xFFu << shift;
            k = s_k;
            __syncthreads();
        }
        uint32_t T = prefix;
        int keq = k;
        if (t == 0) s_cnt = 0;
        __syncthreads();
        int* dst = g_idx + dir * B_ * M_ + b * M_;
        for (int i = t; i < N_; i += 1024) {
            uint32_t v = sv[i];
            bool strict = (dir == 0) ? (v > T) : (v < T);
            if (strict) dst[atomicAdd(&s_cnt, 1)] = i;
        }
        __syncthreads();
        if (t == 0) { s_base = s_cnt; s_cnt = 0; }
        __syncthreads();
        for (int i = t; i < N_; i += 1024) {
            if (sv[i] == T) {
                int e = atomicAdd(&s_cnt, 1);
                if (e < keq) dst[s_base + e] = i;
            }
        }
        __syncthreads();
    }
}

__global__ void gather_kernel() {
    int side = blockIdx.z, b = blockIdx.y;
    int m = blockIdx.x * 8 + (threadIdx.x >> 5);
    int c8 = threadIdx.x & 31;
    int j = g_idx[side * B_ * M_ + b * M_ + m];
    uint4 v = ((const uint4*)(g_cat + ((ll)b * N_ + j) * 768 + 512))[c8];
    ((uint4*)(g_ctxh + (((ll)side * B_ + b) * M_ + m) * C_))[c8] = v;
}

// pack_w also performs all the zero-initialization (g_l, g_xm, g_sum/sumsq)
__global__ void pack_w(const float* a0, const float* a1, const float* a2,
                       const float* a3, const float* a4, const float* a5) {
    int i = blockIdx.x * 256 + threadIdx.x;  // 393216 threads
    const float* p[6] = {a0, a1, a2, a3, a4, a5};
    g_Wh[i] = __float2half_rn(p[i >> 16][i & 65535]);
    if (i < 2 * B_ * N_) g_l[i] = 0.f;
    if (i < B_ * C_) g_xm[i] = 0.f;
    if (i < C_) { g_sum[i] = 0.0; g_sumsq[i] = 0.0; }
}

__global__ void pack_b(const float* b0, const float* b1, const float* b2,
                       const float* b3, const float* b4, const float* b5) {
    int i = threadIdx.x + blockIdx.x * 256;
    const float* p[6] = {b0, b1, b2, b3, b4, b5};
    int grp = i >> 9, k = i & 511;
    g_bp[i] = p[(grp << 1) | (k >> 8)][k & 255];
}

__global__ void combine_w(const float* __restrict__ Wf,
                          const float* __restrict__ Wo_s, const float* __restrict__ Wo_g,
                          const float* __restrict__ bf,
                          const float* __restrict__ bo_s, const float* __restrict__ bo_g) {
    int d = blockIdx.x, t = threadIdx.x;
    __shared__ float wf[512];
    wf[t] = Wf[d * 512 + t];
    wf[t + 256] = Wf[d * 512 + 256 + t];
    __syncthreads();
    float a0 = 0.f, a1 = 0.f;
#pragma unroll 4
    for (int e = 0; e < 256; e++) {
        a0 += wf[e] * Wo_s[e * 256 + t];
        a1 += wf[256 + e] * Wo_g[e * 256 + t];
    }
    g_W3[d * 768 + t] = __float2half_rn(a0);
    g_W3[d * 768 + 256 + t] = __float2half_rn(a1);
    g_W3[d * 768 + 512 + t] = __float2half_rn(wf[t] + wf[256 + t]);
    if (t == 0) {
        float bc = bf[d];
        for (int e = 0; e < 256; e++) bc += wf[e] * bo_s[e] + wf[256 + e] * bo_g[e];
        g_bc[d] = bc;
    }
}

__global__ void bn_finalize(const float* __restrict__ gamma, const float* __restrict__ beta) {
    int d = threadIdx.x;
    double cnt = (double)B_ * N_;
    double mu = g_sum[d] / cnt;
    double var = g_sumsq[d] / cnt - mu * mu;
    float w = gamma[d] * rsqrtf((float)var + EPS_);
    g_bnw[d] = w;
    g_bnb[d] = beta[d] - (float)mu * w;
}

__global__ void bn_final(float* __restrict__ out) {
    int i = blockIdx.x * 256 + threadIdx.x;  // N/4 per (d,b)
    int d = blockIdx.y, b = blockIdx.z;
    ll base = ((ll)b * C_ + d) * N_;
    uint2 raw = ((const uint2*)(g_Ph + base))[i];
    float2 f0 = __half22float2(*(__half2*)&raw.x);
    float2 f1 = __half22float2(*(__half2*)&raw.y);
    float w = g_bnw[d], bb = g_bnb[d];
    float4 o;
    o.x = fmaxf(f0.x * w + bb, 0.f);
    o.y = fmaxf(f0.y * w + bb, 0.f);
    o.z = fmaxf(f1.x * w + bb, 0.f);
    o.w = fmaxf(f1.y * w + bb, 0.f);
    ((float4*)(out + base))[i] = o;
}

// ---------------- fp16 TN GEMM: 3-stage cp.async pipeline ----------------
// EPI: 0 none, 1 ex2(h2)+rowsum (scale pre-folds log2e), 2 div-by-l
__device__ __forceinline__ void load_stage(uint32_t sb, const __half* A, const __half* Bg,
                                           int row0, int col0, int lda, int ldb,
                                           int k0, int tid) {
#pragma unroll
    for (int r = 0; r < 4; r++) {
        int lin = tid + r * 256;
        int row = lin >> 3, f4 = lin & 7;
        uint32_t so = (uint32_t)((row * 8 + (f4 ^ (row & 7))) * 16);
        cp16(sb + so, A + (ll)(row0 + row) * lda + k0 + f4 * 8);
        cp16(sb + 16384 + so, Bg + (ll)(col0 + row) * ldb + k0 + f4 * 8);
    }
}

template <int BIAS, int EPI, bool STATS>
__global__ __launch_bounds__(256, 2)
void gemm_tn(const __half* __restrict__ A, ll sA, ll sA2, int lda,
             const __half* __restrict__ Bg, ll sB, ll sB2, int ldb,
             __half* __restrict__ Cm, ll sC, ll sC2, int ldc, int Kd,
             const float* __restrict__ bias, int biasStr,
             float scale, double* stS, double* stQ,
             float* lrow, ll sL) {
    extern __shared__ char smc[];
    const uint32_t smu = (uint32_t)__cvta_generic_to_shared(smc);
    const int bz = blockIdx.z, side = bz >> 4, b = bz & 15;
    A += (ll)b * sA + (ll)side * sA2;
    Bg += (ll)b * sB + (ll)side * sB2;
    Cm += (ll)b * sC + (ll)side * sC2;
    if (BIAS) bias += side * biasStr;
    if (EPI) lrow += (ll)bz * sL;
    const int row0 = blockIdx.y * 128, col0 = blockIdx.x * 128;
    const int tid = threadIdx.x, lane = tid & 31, warp = tid >> 5;
    const int wm = warp >> 2, wn = warp & 3;
    const int rA = lane & 15, selA = lane >> 4;
    const int tb = lane & 15, rB = tb & 7, midB = tb >> 3;

    float acc[4][4][4];
#pragma unroll
    for (int i = 0; i < 4; i++)
#pragma unroll
        for (int j = 0; j < 4; j++)
#pragma unroll
            for (int q = 0; q < 4; q++) acc[i][j][q] = 0.f;

    const int nT = Kd / 64;
    load_stage(smu, A, Bg, row0, col0, lda, ldb, 0, tid); cp_commit();
    load_stage(smu + 32768, A, Bg, row0, col0, lda, ldb, 64, tid); cp_commit();

    for (int t = 0; t < nT; t++) {
        if (t + 2 < nT)
            load_stage(smu + (uint32_t)(((t + 2) % 3) * 32768), A, Bg,
                       row0, col0, lda, ldb, (t + 2) * 64, tid);
        cp_commit();
        cp_wait<2>();
        __syncthreads();

        uint32_t Au = smu + (uint32_t)((t % 3) * 32768);
        uint32_t Bu = Au + 16384;
#pragma unroll
        for (int kt = 0; kt < 4; kt++) {
            uint32_t af[4][4], bf4[4][2];
#pragma unroll
            for (int mt = 0; mt < 4; mt++) {
                int row = wm * 64 + mt * 16 + rA;
                int u = kt * 2 + selA;
                ldsm_x4(af[mt], Au + (uint32_t)((row * 8 + (u ^ (row & 7))) * 16));
            }
#pragma unroll
            for (int nt = 0; nt < 4; nt++) {
                int row = wn * 32 + nt * 8 + rB;
                int u = kt * 2 + midB;
                ldsm_x2(bf4[nt], Bu + (uint32_t)((row * 8 + (u ^ (row & 7))) * 16));
            }
#pragma unroll
            for (int mt = 0; mt < 4; mt++)
#pragma unroll
                for (int nt = 0; nt < 4; nt++)
                    mma_f16(acc[mt][nt], af[mt], bf4[nt]);
        }
        __syncthreads();
    }

    const int gr = lane >> 2, gc = (lane & 3) * 2;
#pragma unroll
    for (int mt = 0; mt < 4; mt++) {
        int r0 = row0 + wm * 64 + mt * 16 + gr;
        float inv0 = 1.f, inv1 = 1.f;
        if (EPI == 2) { inv0 = 1.f / lrow[r0]; inv1 = 1.f / lrow[r0 + 8]; }
        float s0 = 0.f, q0 = 0.f, s1 = 0.f, q1 = 0.f;
#pragma unroll
        for (int nt = 0; nt < 4; nt++) {
            int col = col0 + wn * 32 + nt * 8 + gc;
            float v0x = acc[mt][nt][0] * scale, v0y = acc[mt][nt][1] * scale;
            float v1x = acc[mt][nt][2] * scale, v1y = acc[mt][nt][3] * scale;
            if (BIAS == 1) {
                float bx = bias[col], by = bias[col + 1];
                v0x += bx; v0y += by; v1x += bx; v1y += by;
            } else if (BIAS == 2) {
                float b0v = bias[r0], b1v = bias[r0 + 8];
                v0x += b0v; v0y += b0v; v1x += b1v; v1y += b1v;
            }
            if (EPI == 1) {
                __half2 h0 = __floats2half2_rn(v0x, v0y);
                __half2 h1 = __floats2half2_rn(v1x, v1y);
                uint32_t e0 = ex2_h2(*(uint32_t*)&h0);
                uint32_t e1 = ex2_h2(*(uint32_t*)&h1);
                float2 f0 = __half22float2(*(__half2*)&e0);
                float2 f1 = __half22float2(*(__half2*)&e1);
                s0 += f0.x + f0.y; s1 += f1.x + f1.y;
                *(uint32_t*)(Cm + (ll)r0 * ldc + col) = e0;
                *(uint32_t*)(Cm + (ll)(r0 + 8) * ldc + col) = e1;
                continue;
            }
            if (EPI == 2) { v0x *= inv0; v0y *= inv0; v1x *= inv1; v1y *= inv1; }
            if (STATS) {
                s0 += v0x + v0y; q0 += v0x * v0x + v0y * v0y;
                s1 += v1x + v1y; q1 += v1x * v1x + v1y * v1y;
            }
            *(__half2*)(Cm + (ll)r0 * ldc + col) = __floats2half2_rn(v0x, v0y);
            *(__half2*)(Cm + (ll)(r0 + 8) * ldc + col) = __floats2half2_rn(v1x, v1y);
        }
        if (EPI == 1) {
            s0 += __shfl_xor_sync(0xffffffffu, s0, 1); s0 += __shfl_xor_sync(0xffffffffu, s0, 2);
            s1 += __shfl_xor_sync(0xffffffffu, s1, 1); s1 += __shfl_xor_sync(0xffffffffu, s1, 2);
            if ((lane & 3) == 0) {
                atomicAdd(&lrow[r0], s0);
                atomicAdd(&lrow[r0 + 8], s1);
            }
        }
        if (STATS) {
            s0 += __shfl_xor_sync(0xffffffffu, s0, 1); s0 += __shfl_xor_sync(0xffffffffu, s0, 2);
            q0 += __shfl_xor_sync(0xffffffffu, q0, 1); q0 += __shfl_xor_sync(0xffffffffu, q0, 2);
            s1 += __shfl_xor_sync(0xffffffffu, s1, 1); s1 += __shfl_xor_sync(0xffffffffu, s1, 2);
            q1 += __shfl_xor_sync(0xffffffffu, q1, 1); q1 += __shfl_xor_sync(0xffffffffu, q1, 2);
            if ((lane & 3) == 0) {
                atomicAdd(&stS[r0], (double)s0);
                atomicAdd(&stQ[r0], (double)q0);
                atomicAdd(&stS[r0 + 8], (double)s1);
                atomicAdd(&stQ[r0 + 8], (double)q1);
            }
        }
    }
}

template <int BIAS, int EPI, bool STATS>
static void launch_tn(const __half* A, ll sA, ll sA2, int lda,
                      const __half* Bg, ll sB, ll sB2, int ldb,
                      __half* Cm, ll sC, ll sC2, int ldc,
                      int Md, int Nd, int Kd,
                      const float* bias, int biasStr,
                      float scale, int batch,
                      double* stS, double* stQ, float* lrow, ll sL) {
    cudaFuncSetAttribute(gemm_tn<BIAS, EPI, STATS>,
                         cudaFuncAttributeMaxDynamicSharedMemorySize, 98304);
    dim3 grid(Nd / 128, Md / 128, batch);
    gemm_tn<BIAS, EPI, STATS><<<grid, 256, 98304>>>(
        A, sA, sA2, lda, Bg, sB, sB2, ldb, Cm, sC, sC2, ldc, Kd,
        bias, biasStr, scale, stS, stQ, lrow, sL);
}

// ---------------- driver ----------------
extern "C" void kernel_launch(void* const* d_in, const int* in_sizes, int n_in,
                              void* d_out, int out_size) {
    const float* x = (const float*)d_in[0];
    int pb = (n_in > 1 && in_sizes[1] == 1) ? 2 : 1;
    const float* P[20];
    for (int i = 0; i < 20; i++) P[i] = (const float*)d_in[pb + i];
    float* out = (float*)d_out;

    __half *cat, *ctxh, *Qh, *Kh, *Vth, *Sh, *Ph, *Wh, *W3;
    float *bp, *bc, *lptr;
    double *stS, *stQ;
    cudaGetSymbolAddress((void**)&cat, g_cat);
    cudaGetSymbolAddress((void**)&ctxh, g_ctxh);
    cudaGetSymbolAddress((void**)&Qh, g_Qh);
    cudaGetSymbolAddress((void**)&Kh, g_Kh);
    cudaGetSymbolAddress((void**)&Vth, g_Vth);
    cudaGetSymbolAddress((void**)&Sh, g_Sh);
    cudaGetSymbolAddress((void**)&Ph, g_Ph);
    cudaGetSymbolAddress((void**)&Wh, g_Wh);
    cudaGetSymbolAddress((void**)&W3, g_W3);
    cudaGetSymbolAddress((void**)&bp, g_bp);
    cudaGetSymbolAddress((void**)&bc, g_bc);
    cudaGetSymbolAddress((void**)&lptr, g_l);
    cudaGetSymbolAddress((void**)&stS, g_sum);
    cudaGetSymbolAddress((void**)&stQ, g_sumsq);

    const int CC = C_ * C_;
    const float LOG2E = 1.4426950408889634f;

    pack_w<<<1536, 256>>>(P[0], P[8], P[2], P[10], P[4], P[12]);  // also zeros l/xm/stats
    transpose_kernel<<<dim3(N_ / 32, C_ / 32, B_), dim3(32, 8)>>>(x);
    score_kernel<<<dim3(N_ / 256, B_), 256>>>(x);
    select_kernel<<<B_, 1024>>>();
    gather_kernel<<<dim3(M_ / 8, B_, 2), 256>>>();
    pack_b<<<6, 256>>>(P[1], P[9], P[3], P[11], P[5], P[13]);
    combine_w<<<256, 256>>>(P[16], P[6], P[14], P[17], P[7], P[15]);

    // Q (both sides)
    launch_tn<1, 0, false>(cat + 512, (ll)N_ * 768, 0, 768,
                           Wh, 0, 0, C_,
                           Qh, (ll)N_ * 512, 0, 512,
                           N_, 512, C_, bp, 0, 1.f, B_, nullptr, nullptr, nullptr, 0);
    // K
    launch_tn<1, 0, false>(ctxh, (ll)M_ * C_, (ll)B_ * M_ * C_, C_,
                           Wh + 2 * CC, 0, CC, C_,
                           Kh, (ll)M_ * C_, (ll)B_ * M_ * C_, C_,
                           M_, C_, C_, bp + 512, 256, 1.f, 2 * B_, nullptr, nullptr, nullptr, 0);
    // V^T
    launch_tn<2, 0, false>(Wh + 4 * CC, 0, CC, C_,
                           ctxh, (ll)M_ * C_, (ll)B_ * M_ * C_, C_,
                           Vth, (ll)C_ * M_, (ll)B_ * C_ * M_, M_,
                           C_, M_, C_, bp + 1024, 256, 1.f, 2 * B_, nullptr, nullptr, nullptr, 0);
    // S~ = 2^(Q·K^T * log2e/16), row sums
    launch_tn<0, 1, false>(Qh, (ll)N_ * 512, (ll)C_, 512,
                           Kh, (ll)M_ * C_, (ll)B_ * M_ * C_, C_,
                           Sh, (ll)N_ * M_, (ll)B_ * N_ * M_, M_,
                           N_, M_, C_, nullptr, 0, LOG2E / 16.f, 2 * B_,
                           nullptr, nullptr, lptr, N_);
    // Y = (S~·V)/l -> cat slots
    launch_tn<0, 2, false>(Sh, (ll)N_ * M_, (ll)B_ * N_ * M_, M_,
                           Vth, (ll)C_ * M_, (ll)B_ * C_ * M_, M_,
                           cat, (ll)N_ * 768, 256, 768,
                           N_, C_, M_, nullptr, 0, 1.f, 2 * B_,
                           nullptr, nullptr, lptr, N_);
    // fuse + BN stats
    launch_tn<2, 0, true>(W3, 0, 0, 768,
                          cat, (ll)N_ * 768, 0, 768,
                          Ph, (ll)C_ * N_, 0, N_,
                          C_, N_, 768, bc, 0, 1.f, B_, stS, stQ, nullptr, 0);

    bn_finalize<<<1, 256>>>(P[18], P[19]);
    bn_final<<<dim3(N_ / 1024, C_, B_), 256>>>(out);
}